// round 13
// baseline (speedup 1.0000x reference)
#include <cuda_runtime.h>
#include <math_constants.h>

#define L_LEN  512
#define D_DIM  4096
#define TOPK   12
#define CPA    4           // channels per block (1 warp per channel, 4 warps/CTA)
#define PADA   516         // row pitch (%32==4 -> conflict-free staging; even -> 8B align)

__device__ __forceinline__ int brev9(int x) { return (int)(__brev((unsigned)x) >> 23); }
// XOR swizzle: conflict-free for both {r*32+lane} and {lane*16+r} warp patterns
__device__ __forceinline__ int swz(int u)   { return u ^ (u >> 5); }

// 16th roots of unity: C16[j] = exp(-2*pi*i*j/16)
__device__ constexpr float C16R[8] = { 1.0f,  0.92387953251f,  0.70710678119f,  0.38268343236f,
                                       0.0f, -0.38268343236f, -0.70710678119f, -0.92387953251f };
__device__ constexpr float C16I[8] = { 0.0f, -0.38268343236f, -0.70710678119f, -0.92387953251f,
                                      -1.0f, -0.92387953251f, -0.70710678119f, -0.38268343236f };

// DIF butterfly: (a,b) -> (a+b, (a-b)*w)
__device__ __forceinline__ void bf_dif(float& ar, float& ai, float& br, float& bi,
                                       float wr, float wi) {
    float tr = ar - br, ti = ai - bi;
    ar += br; ai += bi;
    br = tr * wr - ti * wi;
    bi = tr * wi + ti * wr;
}
__device__ __forceinline__ void bf_dif1(float& ar, float& ai, float& br, float& bi) {
    float tr = ar - br, ti = ai - bi;
    ar += br; ai += bi; br = tr; bi = ti;
}
__device__ __forceinline__ void bf_difmi(float& ar, float& ai, float& br, float& bi) {
    float tr = ar - br, ti = ai - bi;        // *( -i ): (tr,ti) -> (ti, -tr)
    ar += br; ai += bi; br = ti; bi = -tr;
}
// DIT (inverse) butterfly with conj(w): (a,b) -> (a + b*conj(w), a - b*conj(w))
__device__ __forceinline__ void bf_dit(float& ar, float& ai, float& br, float& bi,
                                       float wr, float wi) {
    float rr = br * wr + bi * wi;
    float ri = bi * wr - br * wi;
    br = ar - rr; bi = ai - ri;
    ar += rr; ai += ri;
}
__device__ __forceinline__ void bf_dit1(float& ar, float& ai, float& br, float& bi) {
    float rr = br, ri = bi;
    br = ar - rr; bi = ai - ri;
    ar += rr; ai += ri;
}
__device__ __forceinline__ void bf_ditmi(float& ar, float& ai, float& br, float& bi) {
    float rr = -bi, ri = br;                 // b * conj(-i) = b * i
    br = ar - rr; bi = ai - ri;
    ar += rr; ai += ri;
}
// real-output-only DIT butterfly: imag outputs dropped (inputs still complex)
__device__ __forceinline__ void bf_dit_re(float& ar, float& br, float bi,
                                          float wr, float wi) {
    float rr = br * wr + bi * wi;
    br = ar - rr;
    ar += rr;
}

// ---------------------------------------------------------------------------
// Fused: per-channel FFT cross-correlation -> top-12 + softmax -> gather of V.
// One warp per channel, 4 channels / 128 threads, 2 smem tiles (16.5 KB).
// 10 CTAs/SM (same 40 warps as the 256-thread shape, same 51-reg cap) but
// 4-warp barriers + 2x independent CTAs -> better stall coverage.
// Cross-spectrum via SMEM paired RMW (only non-spilling shape; R7/R11).
// ---------------------------------------------------------------------------
extern "C" __global__ void __launch_bounds__(128, 10)
fused_autocorr_kernel(const float* __restrict__ Q, const float* __restrict__ K,
                      const float* __restrict__ V, float* __restrict__ out) {
    extern __shared__ float smbuf[];
    float* xre = smbuf;                    // [CPA][PADA]  FFT re / V even buf / out tile
    float* xim = xre + CPA * PADA;         // [CPA][PADA]  FFT im / V shift buf

    const int tid  = threadIdx.x;
    const int warp = tid >> 5;
    const int lane = tid & 31;
    const int bh   = blockIdx.x;
    const int b    = bh >> 3;
    const int h    = bh & 7;
    const int cbase = blockIdx.y * CPA;

    // 32-bit global offsets (all tensors < 2^27 elements)
    const unsigned base = (unsigned)b * (L_LEN * D_DIM) + (unsigned)h * 512 + (unsigned)cbase;

    // cooperative float4 staging (Q,K): each thread stages one full 4-channel row
    #pragma unroll
    for (int it = 0; it < 4; ++it) {
        int t = tid + 128 * it;
        unsigned g = base + (unsigned)t * D_DIM;
        float4 q4 = *(const float4*)(Q + g);
        float4 k4 = *(const float4*)(K + g);
        xre[0 * PADA + t] = q4.x;  xre[1 * PADA + t] = q4.y;
        xre[2 * PADA + t] = q4.z;  xre[3 * PADA + t] = q4.w;
        xim[0 * PADA + t] = k4.x;  xim[1 * PADA + t] = k4.y;
        xim[2 * PADA + t] = k4.z;  xim[3 * PADA + t] = k4.w;
    }
    // L2 prefetch of V: consumed after the FFT; warms L2 during compute
    #pragma unroll
    for (int it = 0; it < 4; ++it) {
        const float* pv = V + base + (unsigned)(tid + 128 * it) * D_DIM;
        asm volatile("prefetch.global.L2 [%0];" :: "l"(pv));
    }
    __syncthreads();

    float* re = xre + warp * PADA;
    float* im = xim + warp * PADA;

    // base twiddle: t1 = w^lane, w = exp(-2*pi*i/512)
    float t1i, t1r;
    __sincosf((float)lane * -0.01227184630f, &t1i, &t1r);

    // load channel into registers, layout A (u = r*32 + lane)
    float cre[16], cim[16];
    #pragma unroll
    for (int r = 0; r < 16; ++r) {
        cre[r] = re[r * 32 + lane];
        cim[r] = im[r * 32 + lane];
    }
    __syncwarp();

    // ---- forward DIF, layout A ----
    #pragma unroll
    for (int r = 0; r < 8; ++r) {          // s=8, m=256
        float wr = t1r * C16R[r] - t1i * C16I[r];
        float wi = t1r * C16I[r] + t1i * C16R[r];
        bf_dif(cre[r], cim[r], cre[r + 8], cim[r + 8], wr, wi);
    }
    {                                       // s=7..5 (bases recomputed from t1)
        float t2r = t1r * t1r - t1i * t1i, t2i = 2.0f * t1r * t1i;
        #pragma unroll
        for (int g = 0; g < 2; ++g)
            #pragma unroll
            for (int j = 0; j < 4; ++j) {
                float wr = t2r * C16R[2 * j] - t2i * C16I[2 * j];
                float wi = t2r * C16I[2 * j] + t2i * C16R[2 * j];
                int r = g * 8 + j;
                bf_dif(cre[r], cim[r], cre[r + 4], cim[r + 4], wr, wi);
            }
        float t4r = t2r * t2r - t2i * t2i, t4i = 2.0f * t2r * t2i;   // s=6
        #pragma unroll
        for (int g = 0; g < 4; ++g) {
            int r = g * 4;
            bf_dif(cre[r],     cim[r],     cre[r + 2], cim[r + 2], t4r, t4i);
            bf_dif(cre[r + 1], cim[r + 1], cre[r + 3], cim[r + 3], t4i, -t4r);
        }
        float t8r = t4r * t4r - t4i * t4i, t8i = 2.0f * t4r * t4i;   // s=5
        #pragma unroll
        for (int g = 0; g < 8; ++g) {
            int r = g * 2;
            bf_dif(cre[r], cim[r], cre[r + 1], cim[r + 1], t8r, t8i);
        }
    }
    // ---- forward: shuffle stage m=16 ----
    {
        float swi, swr;
        __sincosf((float)(lane & 15) * -0.19634954085f, &swi, &swr);
        const bool hi = (lane & 16) != 0;
        #pragma unroll
        for (int r = 0; r < 16; ++r) {
            float orr = __shfl_xor_sync(0xffffffffu, cre[r], 16);
            float oii = __shfl_xor_sync(0xffffffffu, cim[r], 16);
            float sr = cre[r] + orr, si = cim[r] + oii;
            float tr = orr - cre[r], ti = oii - cim[r];    // (a-b) on hi lanes
            float pr = tr * swr - ti * swi;
            float pi = tr * swi + ti * swr;
            cre[r] = hi ? pr : sr;
            cim[r] = hi ? pi : si;
        }
    }
    // ---- transpose A -> B through swizzled SMEM ----
    #pragma unroll
    for (int r = 0; r < 16; ++r) {
        int v = swz(r * 32 + lane);
        re[v] = cre[r];  im[v] = cim[r];
    }
    __syncwarp();
    #pragma unroll
    for (int r = 0; r < 16; ++r) {
        int v = swz(lane * 16 + r);
        cre[r] = re[v];  cim[r] = im[v];
    }
    __syncwarp();
    // ---- forward DIF, layout B (all-constant twiddles) ----
    #pragma unroll
    for (int r = 0; r < 8; ++r) {          // s=3, m=8
        if (r == 0)      bf_dif1 (cre[0], cim[0], cre[8],  cim[8]);
        else if (r == 4) bf_difmi(cre[4], cim[4], cre[12], cim[12]);
        else bf_dif(cre[r], cim[r], cre[r + 8], cim[r + 8], C16R[r], C16I[r]);
    }
    #pragma unroll
    for (int g = 0; g < 2; ++g)            // s=2, m=4
        #pragma unroll
        for (int j = 0; j < 4; ++j) {
            int r = g * 8 + j;
            if (j == 0)      bf_dif1 (cre[r], cim[r], cre[r + 4], cim[r + 4]);
            else if (j == 2) bf_difmi(cre[r], cim[r], cre[r + 4], cim[r + 4]);
            else bf_dif(cre[r], cim[r], cre[r + 4], cim[r + 4], C16R[2 * j], C16I[2 * j]);
        }
    #pragma unroll
    for (int g = 0; g < 4; ++g) {          // s=1, m=2
        int r = g * 4;
        bf_dif1 (cre[r],     cim[r],     cre[r + 2], cim[r + 2]);
        bf_difmi(cre[r + 1], cim[r + 1], cre[r + 3], cim[r + 3]);
    }
    #pragma unroll
    for (int g = 0; g < 8; ++g)            // s=0, m=1
        bf_dif1(cre[g * 2], cim[g * 2], cre[g * 2 + 1], cim[g * 2 + 1]);

    // ---- spill (layout B) for bit-reversed Hermitian cross-spectrum ----
    #pragma unroll
    for (int r = 0; r < 16; ++r) {
        int v = swz(lane * 16 + r);
        re[v] = cre[r];  im[v] = cim[r];
    }
    __syncwarp();

    const float inv_n = 1.0f / 512.0f;
    #pragma unroll
    for (int k = 0; k < 8; ++k) {
        int f = 1 + lane + (k << 5);          // f in [1, 256]
        if (f == 256) {
            int pb = swz(brev9(256));
            float qr = re[pb], kr = im[pb];   // both real at Nyquist
            re[pb] = qr * kr * inv_n;
            im[pb] = 0.f;
        } else {
            int p1 = swz(brev9(f));
            int p2 = swz(brev9(512 - f));
            float ar = re[p1], ai = im[p1];
            float br = re[p2], bi = -im[p2];              // conj(X[512-f])
            float qr = 0.5f * (ar + br), qi = 0.5f * (ai + bi);
            float dr = ar - br,          di = ai - bi;
            float kr = 0.5f * di,        ki = -0.5f * dr;  // (A-B)/(2i)
            float pr = (qr * kr + qi * ki) * inv_n;
            float pi = (qi * kr - qr * ki) * inv_n;
            re[p1] = pr;  im[p1] = pi;
            re[p2] = pr;  im[p2] = -pi;                    // Hermitian partner
        }
    }
    if (lane == 0) {                          // f = 0 (DC), both real
        float v = re[0] * im[0] * inv_n;
        re[0] = v; im[0] = 0.f;
    }
    __syncwarp();

    #pragma unroll
    for (int r = 0; r < 16; ++r) {
        int v = swz(lane * 16 + r);
        cre[r] = re[v];  cim[r] = im[v];
    }
    __syncwarp();

    // ---- inverse DIT, layout B ----
    #pragma unroll
    for (int g = 0; g < 8; ++g)            // s=0
        bf_dit1(cre[g * 2], cim[g * 2], cre[g * 2 + 1], cim[g * 2 + 1]);
    #pragma unroll
    for (int g = 0; g < 4; ++g) {          // s=1
        int r = g * 4;
        bf_dit1 (cre[r],     cim[r],     cre[r + 2], cim[r + 2]);
        bf_ditmi(cre[r + 1], cim[r + 1], cre[r + 3], cim[r + 3]);
    }
    #pragma unroll
    for (int g = 0; g < 2; ++g)            // s=2
        #pragma unroll
        for (int j = 0; j < 4; ++j) {
            int r = g * 8 + j;
            if (j == 0)      bf_dit1 (cre[r], cim[r], cre[r + 4], cim[r + 4]);
            else if (j == 2) bf_ditmi(cre[r], cim[r], cre[r + 4], cim[r + 4]);
            else bf_dit(cre[r], cim[r], cre[r + 4], cim[r + 4], C16R[2 * j], C16I[2 * j]);
        }
    #pragma unroll
    for (int r = 0; r < 8; ++r) {          // s=3
        if (r == 0)      bf_dit1 (cre[0], cim[0], cre[8],  cim[8]);
        else if (r == 4) bf_ditmi(cre[4], cim[4], cre[12], cim[12]);
        else bf_dit(cre[r], cim[r], cre[r + 8], cim[r + 8], C16R[r], C16I[r]);
    }
    // ---- transpose B -> A through swizzled SMEM ----
    #pragma unroll
    for (int r = 0; r < 16; ++r) {
        int v = swz(lane * 16 + r);
        re[v] = cre[r];  im[v] = cim[r];
    }
    __syncwarp();
    #pragma unroll
    for (int r = 0; r < 16; ++r) {
        int v = swz(r * 32 + lane);
        cre[r] = re[v];  cim[r] = im[v];
    }
    __syncwarp();
    // ---- inverse: shuffle stage m=16 (conj tw) ----
    {
        float swi, swr;
        __sincosf((float)(lane & 15) * -0.19634954085f, &swi, &swr);
        const float wr = swr, wi = -swi;
        const bool hi = (lane & 16) != 0;
        #pragma unroll
        for (int r = 0; r < 16; ++r) {
            float rr = cre[r] * wr - cim[r] * wi;   // hi lanes pre-rotate b*conj(w)
            float ri = cre[r] * wi + cim[r] * wr;
            float vr = hi ? rr : cre[r];
            float vi = hi ? ri : cim[r];
            float orr = __shfl_xor_sync(0xffffffffu, vr, 16);
            float oii = __shfl_xor_sync(0xffffffffu, vi, 16);
            cre[r] = hi ? (orr - vr) : (vr + orr);
            cim[r] = hi ? (oii - vi) : (vi + oii);
        }
    }
    // ---- inverse DIT, layout A with imag-output pruning ----
    {
        float t2r = t1r * t1r - t1i * t1i, t2i = 2.0f * t1r * t1i;
        float t4r = t2r * t2r - t2i * t2i, t4i = 2.0f * t2r * t2i;
        float t8r = t4r * t4r - t4i * t4i, t8i = 2.0f * t4r * t4i;
        // s=5: g=0 real-only, g>=1 full
        bf_dit_re(cre[0], cre[1], cim[1], t8r, t8i);
        #pragma unroll
        for (int g = 1; g < 8; ++g) {
            int r = g * 2;
            bf_dit(cre[r], cim[r], cre[r + 1], cim[r + 1], t8r, t8i);
        }
        // s=6: g=0 real-only, g>=1 full
        bf_dit_re(cre[0], cre[2], cim[2], t4r, t4i);
        bf_dit_re(cre[1], cre[3], cim[3], t4i, -t4r);
        #pragma unroll
        for (int g = 1; g < 4; ++g) {
            int r = g * 4;
            bf_dit(cre[r],     cim[r],     cre[r + 2], cim[r + 2], t4r, t4i);
            bf_dit(cre[r + 1], cim[r + 1], cre[r + 3], cim[r + 3], t4i, -t4r);
        }
        // s=7: g=0 real-only, g=1 full
        #pragma unroll
        for (int j = 0; j < 4; ++j) {
            float wr = t2r * C16R[2 * j] - t2i * C16I[2 * j];
            float wi = t2r * C16I[2 * j] + t2i * C16R[2 * j];
            bf_dit_re(cre[j], cre[j + 4], cim[j + 4], wr, wi);
        }
        #pragma unroll
        for (int j = 0; j < 4; ++j) {
            float wr = t2r * C16R[2 * j] - t2i * C16I[2 * j];
            float wi = t2r * C16I[2 * j] + t2i * C16R[2 * j];
            int r = 8 + j;
            bf_dit(cre[r], cim[r], cre[r + 4], cim[r + 4], wr, wi);
        }
        // s=8: all real-only
        #pragma unroll
        for (int r = 0; r < 8; ++r) {
            float wr = t1r * C16R[r] - t1i * C16I[r];
            float wi = t1r * C16I[r] + t1i * C16R[r];
            bf_dit_re(cre[r], cre[r + 8], cim[r + 8], wr, wi);
        }
    }
    // corr (natural order) now in cre[], index u = r*32 + lane

    // ---- spill corr row (natural order) for exact value refetch ----
    #pragma unroll
    for (int r = 0; r < 16; ++r)
        re[r * 32 + lane] = cre[r];
    __syncwarp();

    // ---- top-12: position-packed unique keys + strict-less filter + REDUX ----
    unsigned kp[16];
    {
        const int il = 31 - lane;
        #pragma unroll
        for (int r = 0; r < 16; ++r) {
            unsigned u = __float_as_uint(cre[r]);
            unsigned mono = u ^ ((unsigned)((int)u >> 31) | 0x80000000u);
            kp[r] = (mono & 0xFFFFFE00u) | (unsigned)(480 - 32 * r + il);
        }
    }
    int wx[TOPK];
    unsigned Mprev = 0xFFFFFFFFu;
    #pragma unroll
    for (int it = 0; it < TOPK; ++it) {
        unsigned f0  = kp[0]  < Mprev ? kp[0]  : 0u;
        unsigned f1  = kp[1]  < Mprev ? kp[1]  : 0u;
        unsigned f2  = kp[2]  < Mprev ? kp[2]  : 0u;
        unsigned f3  = kp[3]  < Mprev ? kp[3]  : 0u;
        unsigned f4  = kp[4]  < Mprev ? kp[4]  : 0u;
        unsigned f5  = kp[5]  < Mprev ? kp[5]  : 0u;
        unsigned f6  = kp[6]  < Mprev ? kp[6]  : 0u;
        unsigned f7  = kp[7]  < Mprev ? kp[7]  : 0u;
        unsigned f8  = kp[8]  < Mprev ? kp[8]  : 0u;
        unsigned f9  = kp[9]  < Mprev ? kp[9]  : 0u;
        unsigned f10 = kp[10] < Mprev ? kp[10] : 0u;
        unsigned f11 = kp[11] < Mprev ? kp[11] : 0u;
        unsigned f12 = kp[12] < Mprev ? kp[12] : 0u;
        unsigned f13 = kp[13] < Mprev ? kp[13] : 0u;
        unsigned f14 = kp[14] < Mprev ? kp[14] : 0u;
        unsigned f15 = kp[15] < Mprev ? kp[15] : 0u;
        unsigned a0 = max(f0, f1),   a1 = max(f2, f3);
        unsigned a2 = max(f4, f5),   a3 = max(f6, f7);
        unsigned a4 = max(f8, f9),   a5 = max(f10, f11);
        unsigned a6 = max(f12, f13), a7 = max(f14, f15);
        unsigned b0 = max(a0, a1), b1 = max(a2, a3);
        unsigned b2 = max(a4, a5), b3 = max(a6, a7);
        unsigned lmax = max(max(b0, b1), max(b2, b3));
        unsigned M = __reduce_max_sync(0xffffffffu, lmax);
        Mprev = M;
        wx[it] = 511 - (int)(M & 511u);
    }

    // ---- deferred exact-value refetch (kp now dead) + softmax ----
    float wv[TOPK];
    #pragma unroll
    for (int i = 0; i < TOPK; ++i)
        wv[i] = re[wx[i]];                // broadcast LDS
    {
        float mx = wv[0], ssum = 0.f;
        #pragma unroll
        for (int i = 0; i < TOPK; ++i) { wv[i] = __expf(wv[i] - mx); ssum += wv[i]; }
        float inv = 1.0f / ssum;
        #pragma unroll
        for (int i = 0; i < TOPK; ++i) wv[i] *= inv;
    }

    // ---- build V double buffer in the dead FFT tiles (float4 staging) ----
    // even buf (xre row): ev[t] = v[t], ev[512] = ev[513] = v[511]
    // shift buf (xim row): sh[t] = v[t+1] (t<=510), sh[511] = v[511]
    __syncthreads();                          // all warps done with xre/xim + corr rows
    #pragma unroll
    for (int it = 0; it < 4; ++it) {
        int t = tid + 128 * it;
        unsigned g = base + (unsigned)t * D_DIM;
        float4 v4 = *(const float4*)(V + g);
        xre[0 * PADA + t] = v4.x;  xre[1 * PADA + t] = v4.y;
        xre[2 * PADA + t] = v4.z;  xre[3 * PADA + t] = v4.w;
        if (t > 0) {
            xim[0 * PADA + (t - 1)] = v4.x;
            xim[1 * PADA + (t - 1)] = v4.y;
            xim[2 * PADA + (t - 1)] = v4.z;
            xim[3 * PADA + (t - 1)] = v4.w;
        }
        if (t == 511) {
            #pragma unroll
            for (int j = 0; j < 4; ++j) {
                float vb = (j == 0) ? v4.x : (j == 1) ? v4.y : (j == 2) ? v4.z : v4.w;
                xre[j * PADA + 512] = vb;
                xre[j * PADA + 513] = vb;
                xim[j * PADA + 511] = vb;
            }
        }
    }
    __syncthreads();

    // ---- pair-gather: out[l] = sum_i w_i * v[min(idx_i + l, 511)] ----
    // l = 2*lane + 64*pp; aligned v2 pair from parity-matched buffer.
    {
        unsigned evb = (unsigned)__cvta_generic_to_shared(xre + warp * PADA);
        unsigned shb = (unsigned)__cvta_generic_to_shared(xim + warp * PADA);
        unsigned amaxE = evb + 512u * 4u;     // clamped pair = (v511, v511)
        unsigned amaxO = shb + 510u * 4u;
        unsigned lane8 = (unsigned)lane << 3;

        float acc[16];
        #pragma unroll
        for (int j = 0; j < 16; ++j) acc[j] = 0.f;

        #pragma unroll
        for (int i = 0; i < TOPK; ++i) {
            int idx = wx[i];
            bool odd = (idx & 1) != 0;
            unsigned rowb = odd ? shb : evb;
            unsigned amax = odd ? amaxO : amaxE;
            unsigned ab = rowb + (((unsigned)idx & ~1u) << 2) + lane8;
            float w = wv[i];
            #pragma unroll
            for (int pp = 0; pp < 8; ++pp) {
                unsigned a = ab + (unsigned)(pp * 256);
                a = a < amax ? a : amax;
                float vx, vy;
                asm volatile("ld.shared.v2.f32 {%0, %1}, [%2];"
                             : "=f"(vx), "=f"(vy) : "r"(a));
                acc[2 * pp]     += w * vx;
                acc[2 * pp + 1] += w * vy;
            }
        }
        __syncwarp();                         // all lanes done reading own rows
        #pragma unroll
        for (int pp = 0; pp < 8; ++pp) {      // overwrite own even row with out
            unsigned a = evb + lane8 + (unsigned)(pp * 256);
            asm volatile("st.shared.v2.f32 [%0], {%1, %2};"
                         :: "r"(a), "f"(acc[2 * pp]), "f"(acc[2 * pp + 1]));
        }
    }
    __syncthreads();

    // ---- cooperative coalesced float4 store ----
    #pragma unroll
    for (int it = 0; it < 4; ++it) {
        int t = tid + 128 * it;
        float4 o4;
        o4.x = xre[0 * PADA + t];
        o4.y = xre[1 * PADA + t];
        o4.z = xre[2 * PADA + t];
        o4.w = xre[3 * PADA + t];
        *(float4*)(out + base + (unsigned)t * D_DIM) = o4;
    }
}

// ---------------------------------------------------------------------------
extern "C" void kernel_launch(void* const* d_in, const int* in_sizes, int n_in,
                              void* d_out, int out_size) {
    (void)n_in; (void)out_size;
    const float* Q = (const float*)d_in[0];
    const float* K = (const float*)d_in[1];
    const float* V = (const float*)d_in[2];
    float* out = (float*)d_out;

    const int B = in_sizes[0] / (L_LEN * D_DIM);   // 16

    const int SMEM = (2 * CPA * PADA) * (int)sizeof(float);   // 16512 B
    cudaFuncSetAttribute(fused_autocorr_kernel,
                         cudaFuncAttributeMaxDynamicSharedMemorySize, SMEM);

    dim3 grid(B * 8, 512 / CPA);   // (128, 128)
    fused_autocorr_kernel<<<grid, 128, SMEM>>>(Q, K, V, out);
}

// round 14
// speedup vs baseline: 1.2406x; 1.2406x over previous
#include <cuda_runtime.h>
#include <math_constants.h>

#define L_LEN  512
#define D_DIM  4096
#define TOPK   12
#define CPA    8           // channels per block
#define PADA   516         // row pitch (%32==4 -> conflict-free coop transpose; even -> 8B align)

__device__ __forceinline__ int brev9(int x) { return (int)(__brev((unsigned)x) >> 23); }
// XOR swizzle: conflict-free for both {r*32+lane} and {lane*16+r} warp patterns
__device__ __forceinline__ int swz(int u)   { return u ^ (u >> 5); }

// 16th roots of unity: C16[j] = exp(-2*pi*i*j/16)
__device__ constexpr float C16R[8] = { 1.0f,  0.92387953251f,  0.70710678119f,  0.38268343236f,
                                       0.0f, -0.38268343236f, -0.70710678119f, -0.92387953251f };
__device__ constexpr float C16I[8] = { 0.0f, -0.38268343236f, -0.70710678119f, -0.92387953251f,
                                      -1.0f, -0.92387953251f, -0.70710678119f, -0.38268343236f };

// DIF butterfly: (a,b) -> (a+b, (a-b)*w)
__device__ __forceinline__ void bf_dif(float& ar, float& ai, float& br, float& bi,
                                       float wr, float wi) {
    float tr = ar - br, ti = ai - bi;
    ar += br; ai += bi;
    br = tr * wr - ti * wi;
    bi = tr * wi + ti * wr;
}
__device__ __forceinline__ void bf_dif1(float& ar, float& ai, float& br, float& bi) {
    float tr = ar - br, ti = ai - bi;
    ar += br; ai += bi; br = tr; bi = ti;
}
__device__ __forceinline__ void bf_difmi(float& ar, float& ai, float& br, float& bi) {
    float tr = ar - br, ti = ai - bi;        // *( -i ): (tr,ti) -> (ti, -tr)
    ar += br; ai += bi; br = ti; bi = -tr;
}
// DIT (inverse) butterfly with conj(w): (a,b) -> (a + b*conj(w), a - b*conj(w))
__device__ __forceinline__ void bf_dit(float& ar, float& ai, float& br, float& bi,
                                       float wr, float wi) {
    float rr = br * wr + bi * wi;
    float ri = bi * wr - br * wi;
    br = ar - rr; bi = ai - ri;
    ar += rr; ai += ri;
}
__device__ __forceinline__ void bf_dit1(float& ar, float& ai, float& br, float& bi) {
    float rr = br, ri = bi;
    br = ar - rr; bi = ai - ri;
    ar += rr; ai += ri;
}
__device__ __forceinline__ void bf_ditmi(float& ar, float& ai, float& br, float& bi) {
    float rr = -bi, ri = br;                 // b * conj(-i) = b * i
    br = ar - rr; bi = ai - ri;
    ar += rr; ai += ri;
}
// real-output-only DIT butterfly: imag outputs dropped (inputs still complex)
__device__ __forceinline__ void bf_dit_re(float& ar, float& br, float bi,
                                          float wr, float wi) {
    float rr = br * wr + bi * wi;
    br = ar - rr;
    ar += rr;
}

// ---------------------------------------------------------------------------
// Fused: per-channel FFT cross-correlation -> top-12 + softmax -> gather of V.
// One warp per channel, 8 channels / 256 threads, 2 smem tiles total.
// R12 structure (best known: 276.6us) + early L2 prefetch of V so the
// post-barrier V staging hits L2 instead of DRAM.
// Cross-spectrum via SMEM paired RMW (only non-spilling shape; R7/R11).
// ---------------------------------------------------------------------------
extern "C" __global__ void __launch_bounds__(256, 5)
fused_autocorr_kernel(const float* __restrict__ Q, const float* __restrict__ K,
                      const float* __restrict__ V, float* __restrict__ out) {
    extern __shared__ float smbuf[];
    float* xre = smbuf;                    // [CPA][PADA]  FFT re / V even buf / out tile
    float* xim = xre + CPA * PADA;         // [CPA][PADA]  FFT im / V shift buf

    const int tid  = threadIdx.x;
    const int warp = tid >> 5;
    const int lane = tid & 31;
    const int bh   = blockIdx.x;
    const int b    = bh >> 3;
    const int h    = bh & 7;
    const int cbase = blockIdx.y * CPA;

    // 32-bit global offsets (all tensors < 2^27 elements)
    const unsigned base = (unsigned)b * (L_LEN * D_DIM) + (unsigned)h * 512 + (unsigned)cbase;
    const int c4 = (tid & 1) << 2;          // 0 or 4
    const int t4 = tid >> 1;                // 0..127

    // cooperative float4 coalesced loads (Q,K), transposed channel-major
    #pragma unroll
    for (int it = 0; it < 4; ++it) {
        int t = t4 + 128 * it;
        unsigned g = base + (unsigned)t * D_DIM + (unsigned)c4;
        float4 q4 = *(const float4*)(Q + g);
        float4 k4 = *(const float4*)(K + g);
        xre[(c4 + 0) * PADA + t] = q4.x;  xre[(c4 + 1) * PADA + t] = q4.y;
        xre[(c4 + 2) * PADA + t] = q4.z;  xre[(c4 + 3) * PADA + t] = q4.w;
        xim[(c4 + 0) * PADA + t] = k4.x;  xim[(c4 + 1) * PADA + t] = k4.y;
        xim[(c4 + 2) * PADA + t] = k4.z;  xim[(c4 + 3) * PADA + t] = k4.w;
    }
    // early L2 prefetch of V (consumed after the FFT, behind a block barrier)
    #pragma unroll
    for (int it = 0; it < 4; ++it) {
        const float* pv = V + base + (unsigned)(t4 + 128 * it) * D_DIM + (unsigned)c4;
        asm volatile("prefetch.global.L2 [%0];" :: "l"(pv));
    }
    __syncthreads();

    float* re = xre + warp * PADA;
    float* im = xim + warp * PADA;

    // base twiddle: t1 = w^lane, w = exp(-2*pi*i/512)
    float t1i, t1r;
    __sincosf((float)lane * -0.01227184630f, &t1i, &t1r);

    // load channel into registers, layout A (u = r*32 + lane)
    float cre[16], cim[16];
    #pragma unroll
    for (int r = 0; r < 16; ++r) {
        cre[r] = re[r * 32 + lane];
        cim[r] = im[r * 32 + lane];
    }
    __syncwarp();

    // ---- forward DIF, layout A ----
    #pragma unroll
    for (int r = 0; r < 8; ++r) {          // s=8, m=256
        float wr = t1r * C16R[r] - t1i * C16I[r];
        float wi = t1r * C16I[r] + t1i * C16R[r];
        bf_dif(cre[r], cim[r], cre[r + 8], cim[r + 8], wr, wi);
    }
    {                                       // s=7..5 (bases recomputed from t1)
        float t2r = t1r * t1r - t1i * t1i, t2i = 2.0f * t1r * t1i;
        #pragma unroll
        for (int g = 0; g < 2; ++g)
            #pragma unroll
            for (int j = 0; j < 4; ++j) {
                float wr = t2r * C16R[2 * j] - t2i * C16I[2 * j];
                float wi = t2r * C16I[2 * j] + t2i * C16R[2 * j];
                int r = g * 8 + j;
                bf_dif(cre[r], cim[r], cre[r + 4], cim[r + 4], wr, wi);
            }
        float t4r = t2r * t2r - t2i * t2i, t4i = 2.0f * t2r * t2i;   // s=6
        #pragma unroll
        for (int g = 0; g < 4; ++g) {
            int r = g * 4;
            bf_dif(cre[r],     cim[r],     cre[r + 2], cim[r + 2], t4r, t4i);
            bf_dif(cre[r + 1], cim[r + 1], cre[r + 3], cim[r + 3], t4i, -t4r);
        }
        float t8r = t4r * t4r - t4i * t4i, t8i = 2.0f * t4r * t4i;   // s=5
        #pragma unroll
        for (int g = 0; g < 8; ++g) {
            int r = g * 2;
            bf_dif(cre[r], cim[r], cre[r + 1], cim[r + 1], t8r, t8i);
        }
    }
    // ---- forward: shuffle stage m=16 ----
    {
        float swi, swr;
        __sincosf((float)(lane & 15) * -0.19634954085f, &swi, &swr);
        const bool hi = (lane & 16) != 0;
        #pragma unroll
        for (int r = 0; r < 16; ++r) {
            float orr = __shfl_xor_sync(0xffffffffu, cre[r], 16);
            float oii = __shfl_xor_sync(0xffffffffu, cim[r], 16);
            float sr = cre[r] + orr, si = cim[r] + oii;
            float tr = orr - cre[r], ti = oii - cim[r];    // (a-b) on hi lanes
            float pr = tr * swr - ti * swi;
            float pi = tr * swi + ti * swr;
            cre[r] = hi ? pr : sr;
            cim[r] = hi ? pi : si;
        }
    }
    // ---- transpose A -> B through swizzled SMEM ----
    #pragma unroll
    for (int r = 0; r < 16; ++r) {
        int v = swz(r * 32 + lane);
        re[v] = cre[r];  im[v] = cim[r];
    }
    __syncwarp();
    #pragma unroll
    for (int r = 0; r < 16; ++r) {
        int v = swz(lane * 16 + r);
        cre[r] = re[v];  cim[r] = im[v];
    }
    __syncwarp();
    // ---- forward DIF, layout B (all-constant twiddles) ----
    #pragma unroll
    for (int r = 0; r < 8; ++r) {          // s=3, m=8
        if (r == 0)      bf_dif1 (cre[0], cim[0], cre[8],  cim[8]);
        else if (r == 4) bf_difmi(cre[4], cim[4], cre[12], cim[12]);
        else bf_dif(cre[r], cim[r], cre[r + 8], cim[r + 8], C16R[r], C16I[r]);
    }
    #pragma unroll
    for (int g = 0; g < 2; ++g)            // s=2, m=4
        #pragma unroll
        for (int j = 0; j < 4; ++j) {
            int r = g * 8 + j;
            if (j == 0)      bf_dif1 (cre[r], cim[r], cre[r + 4], cim[r + 4]);
            else if (j == 2) bf_difmi(cre[r], cim[r], cre[r + 4], cim[r + 4]);
            else bf_dif(cre[r], cim[r], cre[r + 4], cim[r + 4], C16R[2 * j], C16I[2 * j]);
        }
    #pragma unroll
    for (int g = 0; g < 4; ++g) {          // s=1, m=2
        int r = g * 4;
        bf_dif1 (cre[r],     cim[r],     cre[r + 2], cim[r + 2]);
        bf_difmi(cre[r + 1], cim[r + 1], cre[r + 3], cim[r + 3]);
    }
    #pragma unroll
    for (int g = 0; g < 8; ++g)            // s=0, m=1
        bf_dif1(cre[g * 2], cim[g * 2], cre[g * 2 + 1], cim[g * 2 + 1]);

    // ---- spill (layout B) for bit-reversed Hermitian cross-spectrum ----
    #pragma unroll
    for (int r = 0; r < 16; ++r) {
        int v = swz(lane * 16 + r);
        re[v] = cre[r];  im[v] = cim[r];
    }
    __syncwarp();

    const float inv_n = 1.0f / 512.0f;
    #pragma unroll
    for (int k = 0; k < 8; ++k) {
        int f = 1 + lane + (k << 5);          // f in [1, 256]
        if (f == 256) {
            int pb = swz(brev9(256));
            float qr = re[pb], kr = im[pb];   // both real at Nyquist
            re[pb] = qr * kr * inv_n;
            im[pb] = 0.f;
        } else {
            int p1 = swz(brev9(f));
            int p2 = swz(brev9(512 - f));
            float ar = re[p1], ai = im[p1];
            float br = re[p2], bi = -im[p2];              // conj(X[512-f])
            float qr = 0.5f * (ar + br), qi = 0.5f * (ai + bi);
            float dr = ar - br,          di = ai - bi;
            float kr = 0.5f * di,        ki = -0.5f * dr;  // (A-B)/(2i)
            float pr = (qr * kr + qi * ki) * inv_n;
            float pi = (qi * kr - qr * ki) * inv_n;
            re[p1] = pr;  im[p1] = pi;
            re[p2] = pr;  im[p2] = -pi;                    // Hermitian partner
        }
    }
    if (lane == 0) {                          // f = 0 (DC), both real
        float v = re[0] * im[0] * inv_n;
        re[0] = v; im[0] = 0.f;
    }
    __syncwarp();

    #pragma unroll
    for (int r = 0; r < 16; ++r) {
        int v = swz(lane * 16 + r);
        cre[r] = re[v];  cim[r] = im[v];
    }
    __syncwarp();

    // ---- inverse DIT, layout B ----
    #pragma unroll
    for (int g = 0; g < 8; ++g)            // s=0
        bf_dit1(cre[g * 2], cim[g * 2], cre[g * 2 + 1], cim[g * 2 + 1]);
    #pragma unroll
    for (int g = 0; g < 4; ++g) {          // s=1
        int r = g * 4;
        bf_dit1 (cre[r],     cim[r],     cre[r + 2], cim[r + 2]);
        bf_ditmi(cre[r + 1], cim[r + 1], cre[r + 3], cim[r + 3]);
    }
    #pragma unroll
    for (int g = 0; g < 2; ++g)            // s=2
        #pragma unroll
        for (int j = 0; j < 4; ++j) {
            int r = g * 8 + j;
            if (j == 0)      bf_dit1 (cre[r], cim[r], cre[r + 4], cim[r + 4]);
            else if (j == 2) bf_ditmi(cre[r], cim[r], cre[r + 4], cim[r + 4]);
            else bf_dit(cre[r], cim[r], cre[r + 4], cim[r + 4], C16R[2 * j], C16I[2 * j]);
        }
    #pragma unroll
    for (int r = 0; r < 8; ++r) {          // s=3
        if (r == 0)      bf_dit1 (cre[0], cim[0], cre[8],  cim[8]);
        else if (r == 4) bf_ditmi(cre[4], cim[4], cre[12], cim[12]);
        else bf_dit(cre[r], cim[r], cre[r + 8], cim[r + 8], C16R[r], C16I[r]);
    }
    // ---- transpose B -> A through swizzled SMEM ----
    #pragma unroll
    for (int r = 0; r < 16; ++r) {
        int v = swz(lane * 16 + r);
        re[v] = cre[r];  im[v] = cim[r];
    }
    __syncwarp();
    #pragma unroll
    for (int r = 0; r < 16; ++r) {
        int v = swz(r * 32 + lane);
        cre[r] = re[v];  cim[r] = im[v];
    }
    __syncwarp();
    // ---- inverse: shuffle stage m=16 (conj tw) ----
    {
        float swi, swr;
        __sincosf((float)(lane & 15) * -0.19634954085f, &swi, &swr);
        const float wr = swr, wi = -swi;
        const bool hi = (lane & 16) != 0;
        #pragma unroll
        for (int r = 0; r < 16; ++r) {
            float rr = cre[r] * wr - cim[r] * wi;   // hi lanes pre-rotate b*conj(w)
            float ri = cre[r] * wi + cim[r] * wr;
            float vr = hi ? rr : cre[r];
            float vi = hi ? ri : cim[r];
            float orr = __shfl_xor_sync(0xffffffffu, vr, 16);
            float oii = __shfl_xor_sync(0xffffffffu, vi, 16);
            cre[r] = hi ? (orr - vr) : (vr + orr);
            cim[r] = hi ? (oii - vi) : (vi + oii);
        }
    }
    // ---- inverse DIT, layout A with imag-output pruning ----
    {
        float t2r = t1r * t1r - t1i * t1i, t2i = 2.0f * t1r * t1i;
        float t4r = t2r * t2r - t2i * t2i, t4i = 2.0f * t2r * t2i;
        float t8r = t4r * t4r - t4i * t4i, t8i = 2.0f * t4r * t4i;
        // s=5: g=0 real-only, g>=1 full
        bf_dit_re(cre[0], cre[1], cim[1], t8r, t8i);
        #pragma unroll
        for (int g = 1; g < 8; ++g) {
            int r = g * 2;
            bf_dit(cre[r], cim[r], cre[r + 1], cim[r + 1], t8r, t8i);
        }
        // s=6: g=0 real-only, g>=1 full
        bf_dit_re(cre[0], cre[2], cim[2], t4r, t4i);
        bf_dit_re(cre[1], cre[3], cim[3], t4i, -t4r);
        #pragma unroll
        for (int g = 1; g < 4; ++g) {
            int r = g * 4;
            bf_dit(cre[r],     cim[r],     cre[r + 2], cim[r + 2], t4r, t4i);
            bf_dit(cre[r + 1], cim[r + 1], cre[r + 3], cim[r + 3], t4i, -t4r);
        }
        // s=7: g=0 real-only, g=1 full
        #pragma unroll
        for (int j = 0; j < 4; ++j) {
            float wr = t2r * C16R[2 * j] - t2i * C16I[2 * j];
            float wi = t2r * C16I[2 * j] + t2i * C16R[2 * j];
            bf_dit_re(cre[j], cre[j + 4], cim[j + 4], wr, wi);
        }
        #pragma unroll
        for (int j = 0; j < 4; ++j) {
            float wr = t2r * C16R[2 * j] - t2i * C16I[2 * j];
            float wi = t2r * C16I[2 * j] + t2i * C16R[2 * j];
            int r = 8 + j;
            bf_dit(cre[r], cim[r], cre[r + 4], cim[r + 4], wr, wi);
        }
        // s=8: all real-only
        #pragma unroll
        for (int r = 0; r < 8; ++r) {
            float wr = t1r * C16R[r] - t1i * C16I[r];
            float wi = t1r * C16I[r] + t1i * C16R[r];
            bf_dit_re(cre[r], cre[r + 8], cim[r + 8], wr, wi);
        }
    }
    // corr (natural order) now in cre[], index u = r*32 + lane

    // ---- spill corr row (natural order) for exact value refetch ----
    #pragma unroll
    for (int r = 0; r < 16; ++r)
        re[r * 32 + lane] = cre[r];
    __syncwarp();

    // ---- top-12: position-packed unique keys + strict-less filter + REDUX ----
    unsigned kp[16];
    {
        const int il = 31 - lane;
        #pragma unroll
        for (int r = 0; r < 16; ++r) {
            unsigned u = __float_as_uint(cre[r]);
            unsigned mono = u ^ ((unsigned)((int)u >> 31) | 0x80000000u);
            kp[r] = (mono & 0xFFFFFE00u) | (unsigned)(480 - 32 * r + il);
        }
    }
    int wx[TOPK];
    unsigned Mprev = 0xFFFFFFFFu;
    #pragma unroll
    for (int it = 0; it < TOPK; ++it) {
        unsigned f0  = kp[0]  < Mprev ? kp[0]  : 0u;
        unsigned f1  = kp[1]  < Mprev ? kp[1]  : 0u;
        unsigned f2  = kp[2]  < Mprev ? kp[2]  : 0u;
        unsigned f3  = kp[3]  < Mprev ? kp[3]  : 0u;
        unsigned f4  = kp[4]  < Mprev ? kp[4]  : 0u;
        unsigned f5  = kp[5]  < Mprev ? kp[5]  : 0u;
        unsigned f6  = kp[6]  < Mprev ? kp[6]  : 0u;
        unsigned f7  = kp[7]  < Mprev ? kp[7]  : 0u;
        unsigned f8  = kp[8]  < Mprev ? kp[8]  : 0u;
        unsigned f9  = kp[9]  < Mprev ? kp[9]  : 0u;
        unsigned f10 = kp[10] < Mprev ? kp[10] : 0u;
        unsigned f11 = kp[11] < Mprev ? kp[11] : 0u;
        unsigned f12 = kp[12] < Mprev ? kp[12] : 0u;
        unsigned f13 = kp[13] < Mprev ? kp[13] : 0u;
        unsigned f14 = kp[14] < Mprev ? kp[14] : 0u;
        unsigned f15 = kp[15] < Mprev ? kp[15] : 0u;
        unsigned a0 = max(f0, f1),   a1 = max(f2, f3);
        unsigned a2 = max(f4, f5),   a3 = max(f6, f7);
        unsigned a4 = max(f8, f9),   a5 = max(f10, f11);
        unsigned a6 = max(f12, f13), a7 = max(f14, f15);
        unsigned b0 = max(a0, a1), b1 = max(a2, a3);
        unsigned b2 = max(a4, a5), b3 = max(a6, a7);
        unsigned lmax = max(max(b0, b1), max(b2, b3));
        unsigned M = __reduce_max_sync(0xffffffffu, lmax);
        Mprev = M;
        wx[it] = 511 - (int)(M & 511u);
    }

    // ---- deferred exact-value refetch (kp now dead) + softmax ----
    float wv[TOPK];
    #pragma unroll
    for (int i = 0; i < TOPK; ++i)
        wv[i] = re[wx[i]];                // broadcast LDS
    {
        float mx = wv[0], ssum = 0.f;
        #pragma unroll
        for (int i = 0; i < TOPK; ++i) { wv[i] = __expf(wv[i] - mx); ssum += wv[i]; }
        float inv = 1.0f / ssum;
        #pragma unroll
        for (int i = 0; i < TOPK; ++i) wv[i] *= inv;
    }

    // ---- build V double buffer in the dead FFT tiles (float4 staging) ----
    // even buf (xre row): ev[t] = v[t], ev[512] = ev[513] = v[511]
    // shift buf (xim row): sh[t] = v[t+1] (t<=510), sh[511] = v[511]
    __syncthreads();                          // all warps done with xre/xim + corr rows
    #pragma unroll
    for (int it = 0; it < 4; ++it) {
        int t = t4 + 128 * it;
        unsigned g = base + (unsigned)t * D_DIM + (unsigned)c4;
        float4 v4 = *(const float4*)(V + g);
        xre[(c4 + 0) * PADA + t] = v4.x;  xre[(c4 + 1) * PADA + t] = v4.y;
        xre[(c4 + 2) * PADA + t] = v4.z;  xre[(c4 + 3) * PADA + t] = v4.w;
        if (t > 0) {
            xim[(c4 + 0) * PADA + (t - 1)] = v4.x;
            xim[(c4 + 1) * PADA + (t - 1)] = v4.y;
            xim[(c4 + 2) * PADA + (t - 1)] = v4.z;
            xim[(c4 + 3) * PADA + (t - 1)] = v4.w;
        }
        if (t == 511) {
            #pragma unroll
            for (int j = 0; j < 4; ++j) {
                float vb = (j == 0) ? v4.x : (j == 1) ? v4.y : (j == 2) ? v4.z : v4.w;
                xre[(c4 + j) * PADA + 512] = vb;
                xre[(c4 + j) * PADA + 513] = vb;
                xim[(c4 + j) * PADA + 511] = vb;
            }
        }
    }
    __syncthreads();

    // ---- pair-gather: out[l] = sum_i w_i * v[min(idx_i + l, 511)] ----
    // l = 2*lane + 64*pp; aligned v2 pair from parity-matched buffer.
    {
        unsigned evb = (unsigned)__cvta_generic_to_shared(xre + warp * PADA);
        unsigned shb = (unsigned)__cvta_generic_to_shared(xim + warp * PADA);
        unsigned amaxE = evb + 512u * 4u;     // clamped pair = (v511, v511)
        unsigned amaxO = shb + 510u * 4u;
        unsigned lane8 = (unsigned)lane << 3;

        float acc[16];
        #pragma unroll
        for (int j = 0; j < 16; ++j) acc[j] = 0.f;

        #pragma unroll
        for (int i = 0; i < TOPK; ++i) {
            int idx = wx[i];
            bool odd = (idx & 1) != 0;
            unsigned rowb = odd ? shb : evb;
            unsigned amax = odd ? amaxO : amaxE;
            unsigned ab = rowb + (((unsigned)idx & ~1u) << 2) + lane8;
            float w = wv[i];
            #pragma unroll
            for (int pp = 0; pp < 8; ++pp) {
                unsigned a = ab + (unsigned)(pp * 256);
                a = a < amax ? a : amax;
                float vx, vy;
                asm volatile("ld.shared.v2.f32 {%0, %1}, [%2];"
                             : "=f"(vx), "=f"(vy) : "r"(a));
                acc[2 * pp]     += w * vx;
                acc[2 * pp + 1] += w * vy;
            }
        }
        __syncwarp();                         // all lanes done reading own rows
        #pragma unroll
        for (int pp = 0; pp < 8; ++pp) {      // overwrite own even row with out
            unsigned a = evb + lane8 + (unsigned)(pp * 256);
            asm volatile("st.shared.v2.f32 [%0], {%1, %2};"
                         :: "r"(a), "f"(acc[2 * pp]), "f"(acc[2 * pp + 1]));
        }
    }
    __syncthreads();

    // ---- cooperative coalesced float4 store ----
    #pragma unroll
    for (int it = 0; it < 4; ++it) {
        int t = t4 + 128 * it;
        float4 o4;
        o4.x = xre[(c4 + 0) * PADA + t];
        o4.y = xre[(c4 + 1) * PADA + t];
        o4.z = xre[(c4 + 2) * PADA + t];
        o4.w = xre[(c4 + 3) * PADA + t];
        *(float4*)(out + base + (unsigned)t * D_DIM + (unsigned)c4) = o4;
    }
}

// ---------------------------------------------------------------------------
extern "C" void kernel_launch(void* const* d_in, const int* in_sizes, int n_in,
                              void* d_out, int out_size) {
    (void)n_in; (void)out_size;
    const float* Q = (const float*)d_in[0];
    const float* K = (const float*)d_in[1];
    const float* V = (const float*)d_in[2];
    float* out = (float*)d_out;

    const int B = in_sizes[0] / (L_LEN * D_DIM);   // 16

    const int SMEM = (2 * CPA * PADA) * (int)sizeof(float);   // 33024 B
    cudaFuncSetAttribute(fused_autocorr_kernel,
                         cudaFuncAttributeMaxDynamicSharedMemorySize, SMEM);

    dim3 grid(B * 8, 512 / CPA);   // (128, 64)
    fused_autocorr_kernel<<<grid, 256, SMEM>>>(Q, K, V, out);
}

// round 15
// speedup vs baseline: 1.2804x; 1.0321x over previous
#include <cuda_runtime.h>
#include <math_constants.h>

#define L_LEN  512
#define D_DIM  4096
#define TOPK   12
#define CPA    8           // channels per block
#define PADA   516         // row pitch (%32==4 -> conflict-free coop transpose; even -> 8B align)

__device__ __forceinline__ int brev9(int x) { return (int)(__brev((unsigned)x) >> 23); }
// XOR swizzle: conflict-free for both {r*32+lane} and {lane*16+r} warp patterns
__device__ __forceinline__ int swz(int u)   { return u ^ (u >> 5); }

// 16th roots of unity: C16[j] = exp(-2*pi*i*j/16)
__device__ constexpr float C16R[8] = { 1.0f,  0.92387953251f,  0.70710678119f,  0.38268343236f,
                                       0.0f, -0.38268343236f, -0.70710678119f, -0.92387953251f };
__device__ constexpr float C16I[8] = { 0.0f, -0.38268343236f, -0.70710678119f, -0.92387953251f,
                                      -1.0f, -0.92387953251f, -0.70710678119f, -0.38268343236f };

// DIF butterfly: (a,b) -> (a+b, (a-b)*w)
__device__ __forceinline__ void bf_dif(float& ar, float& ai, float& br, float& bi,
                                       float wr, float wi) {
    float tr = ar - br, ti = ai - bi;
    ar += br; ai += bi;
    br = tr * wr - ti * wi;
    bi = tr * wi + ti * wr;
}
__device__ __forceinline__ void bf_dif1(float& ar, float& ai, float& br, float& bi) {
    float tr = ar - br, ti = ai - bi;
    ar += br; ai += bi; br = tr; bi = ti;
}
__device__ __forceinline__ void bf_difmi(float& ar, float& ai, float& br, float& bi) {
    float tr = ar - br, ti = ai - bi;        // *( -i ): (tr,ti) -> (ti, -tr)
    ar += br; ai += bi; br = ti; bi = -tr;
}
// DIT (inverse) butterfly with conj(w): (a,b) -> (a + b*conj(w), a - b*conj(w))
__device__ __forceinline__ void bf_dit(float& ar, float& ai, float& br, float& bi,
                                       float wr, float wi) {
    float rr = br * wr + bi * wi;
    float ri = bi * wr - br * wi;
    br = ar - rr; bi = ai - ri;
    ar += rr; ai += ri;
}
__device__ __forceinline__ void bf_dit1(float& ar, float& ai, float& br, float& bi) {
    float rr = br, ri = bi;
    br = ar - rr; bi = ai - ri;
    ar += rr; ai += ri;
}
__device__ __forceinline__ void bf_ditmi(float& ar, float& ai, float& br, float& bi) {
    float rr = -bi, ri = br;                 // b * conj(-i) = b * i
    br = ar - rr; bi = ai - ri;
    ar += rr; ai += ri;
}
// real-output-only DIT butterfly: imag outputs dropped (inputs still complex)
__device__ __forceinline__ void bf_dit_re(float& ar, float& br, float bi,
                                          float wr, float wi) {
    float rr = br * wr + bi * wi;
    br = ar - rr;
    ar += rr;
}

// ---------------------------------------------------------------------------
// Fused: per-channel FFT cross-correlation -> top-12 + softmax -> gather of V.
// One warp per channel, 8 channels / 256 threads, 2 smem tiles total.
// Cross-spectrum via SMEM paired RMW (only non-spilling shape; R7/R11).
// Inverse FFT tail prunes imaginary outputs (only real corr is consumed).
// Final converged structure (R12): 276.6us, 4.9x over first correct kernel.
// ---------------------------------------------------------------------------
extern "C" __global__ void __launch_bounds__(256, 5)
fused_autocorr_kernel(const float* __restrict__ Q, const float* __restrict__ K,
                      const float* __restrict__ V, float* __restrict__ out) {
    extern __shared__ float smbuf[];
    float* xre = smbuf;                    // [CPA][PADA]  FFT re / V even buf / out tile
    float* xim = xre + CPA * PADA;         // [CPA][PADA]  FFT im / V shift buf

    const int tid  = threadIdx.x;
    const int warp = tid >> 5;
    const int lane = tid & 31;
    const int bh   = blockIdx.x;
    const int b    = bh >> 3;
    const int h    = bh & 7;
    const int cbase = blockIdx.y * CPA;

    // 32-bit global offsets (all tensors < 2^27 elements)
    const unsigned base = (unsigned)b * (L_LEN * D_DIM) + (unsigned)h * 512 + (unsigned)cbase;
    const int c4 = (tid & 1) << 2;          // 0 or 4
    const int t4 = tid >> 1;                // 0..127

    // cooperative float4 coalesced loads (Q,K), transposed channel-major
    #pragma unroll
    for (int it = 0; it < 4; ++it) {
        int t = t4 + 128 * it;
        unsigned g = base + (unsigned)t * D_DIM + (unsigned)c4;
        float4 q4 = *(const float4*)(Q + g);
        float4 k4 = *(const float4*)(K + g);
        xre[(c4 + 0) * PADA + t] = q4.x;  xre[(c4 + 1) * PADA + t] = q4.y;
        xre[(c4 + 2) * PADA + t] = q4.z;  xre[(c4 + 3) * PADA + t] = q4.w;
        xim[(c4 + 0) * PADA + t] = k4.x;  xim[(c4 + 1) * PADA + t] = k4.y;
        xim[(c4 + 2) * PADA + t] = k4.z;  xim[(c4 + 3) * PADA + t] = k4.w;
    }
    __syncthreads();

    float* re = xre + warp * PADA;
    float* im = xim + warp * PADA;

    // base twiddle: t1 = w^lane, w = exp(-2*pi*i/512)
    float t1i, t1r;
    __sincosf((float)lane * -0.01227184630f, &t1i, &t1r);

    // load channel into registers, layout A (u = r*32 + lane)
    float cre[16], cim[16];
    #pragma unroll
    for (int r = 0; r < 16; ++r) {
        cre[r] = re[r * 32 + lane];
        cim[r] = im[r * 32 + lane];
    }
    __syncwarp();

    // ---- forward DIF, layout A ----
    #pragma unroll
    for (int r = 0; r < 8; ++r) {          // s=8, m=256
        float wr = t1r * C16R[r] - t1i * C16I[r];
        float wi = t1r * C16I[r] + t1i * C16R[r];
        bf_dif(cre[r], cim[r], cre[r + 8], cim[r + 8], wr, wi);
    }
    {                                       // s=7..5 (bases recomputed from t1)
        float t2r = t1r * t1r - t1i * t1i, t2i = 2.0f * t1r * t1i;
        #pragma unroll
        for (int g = 0; g < 2; ++g)
            #pragma unroll
            for (int j = 0; j < 4; ++j) {
                float wr = t2r * C16R[2 * j] - t2i * C16I[2 * j];
                float wi = t2r * C16I[2 * j] + t2i * C16R[2 * j];
                int r = g * 8 + j;
                bf_dif(cre[r], cim[r], cre[r + 4], cim[r + 4], wr, wi);
            }
        float t4r = t2r * t2r - t2i * t2i, t4i = 2.0f * t2r * t2i;   // s=6
        #pragma unroll
        for (int g = 0; g < 4; ++g) {
            int r = g * 4;
            bf_dif(cre[r],     cim[r],     cre[r + 2], cim[r + 2], t4r, t4i);
            bf_dif(cre[r + 1], cim[r + 1], cre[r + 3], cim[r + 3], t4i, -t4r);
        }
        float t8r = t4r * t4r - t4i * t4i, t8i = 2.0f * t4r * t4i;   // s=5
        #pragma unroll
        for (int g = 0; g < 8; ++g) {
            int r = g * 2;
            bf_dif(cre[r], cim[r], cre[r + 1], cim[r + 1], t8r, t8i);
        }
    }
    // ---- forward: shuffle stage m=16 ----
    {
        float swi, swr;
        __sincosf((float)(lane & 15) * -0.19634954085f, &swi, &swr);
        const bool hi = (lane & 16) != 0;
        #pragma unroll
        for (int r = 0; r < 16; ++r) {
            float orr = __shfl_xor_sync(0xffffffffu, cre[r], 16);
            float oii = __shfl_xor_sync(0xffffffffu, cim[r], 16);
            float sr = cre[r] + orr, si = cim[r] + oii;
            float tr = orr - cre[r], ti = oii - cim[r];    // (a-b) on hi lanes
            float pr = tr * swr - ti * swi;
            float pi = tr * swi + ti * swr;
            cre[r] = hi ? pr : sr;
            cim[r] = hi ? pi : si;
        }
    }
    // ---- transpose A -> B through swizzled SMEM ----
    #pragma unroll
    for (int r = 0; r < 16; ++r) {
        int v = swz(r * 32 + lane);
        re[v] = cre[r];  im[v] = cim[r];
    }
    __syncwarp();
    #pragma unroll
    for (int r = 0; r < 16; ++r) {
        int v = swz(lane * 16 + r);
        cre[r] = re[v];  cim[r] = im[v];
    }
    __syncwarp();
    // ---- forward DIF, layout B (all-constant twiddles) ----
    #pragma unroll
    for (int r = 0; r < 8; ++r) {          // s=3, m=8
        if (r == 0)      bf_dif1 (cre[0], cim[0], cre[8],  cim[8]);
        else if (r == 4) bf_difmi(cre[4], cim[4], cre[12], cim[12]);
        else bf_dif(cre[r], cim[r], cre[r + 8], cim[r + 8], C16R[r], C16I[r]);
    }
    #pragma unroll
    for (int g = 0; g < 2; ++g)            // s=2, m=4
        #pragma unroll
        for (int j = 0; j < 4; ++j) {
            int r = g * 8 + j;
            if (j == 0)      bf_dif1 (cre[r], cim[r], cre[r + 4], cim[r + 4]);
            else if (j == 2) bf_difmi(cre[r], cim[r], cre[r + 4], cim[r + 4]);
            else bf_dif(cre[r], cim[r], cre[r + 4], cim[r + 4], C16R[2 * j], C16I[2 * j]);
        }
    #pragma unroll
    for (int g = 0; g < 4; ++g) {          // s=1, m=2
        int r = g * 4;
        bf_dif1 (cre[r],     cim[r],     cre[r + 2], cim[r + 2]);
        bf_difmi(cre[r + 1], cim[r + 1], cre[r + 3], cim[r + 3]);
    }
    #pragma unroll
    for (int g = 0; g < 8; ++g)            // s=0, m=1
        bf_dif1(cre[g * 2], cim[g * 2], cre[g * 2 + 1], cim[g * 2 + 1]);

    // ---- spill (layout B) for bit-reversed Hermitian cross-spectrum ----
    #pragma unroll
    for (int r = 0; r < 16; ++r) {
        int v = swz(lane * 16 + r);
        re[v] = cre[r];  im[v] = cim[r];
    }
    __syncwarp();

    const float inv_n = 1.0f / 512.0f;
    #pragma unroll
    for (int k = 0; k < 8; ++k) {
        int f = 1 + lane + (k << 5);          // f in [1, 256]
        if (f == 256) {
            int pb = swz(brev9(256));
            float qr = re[pb], kr = im[pb];   // both real at Nyquist
            re[pb] = qr * kr * inv_n;
            im[pb] = 0.f;
        } else {
            int p1 = swz(brev9(f));
            int p2 = swz(brev9(512 - f));
            float ar = re[p1], ai = im[p1];
            float br = re[p2], bi = -im[p2];              // conj(X[512-f])
            float qr = 0.5f * (ar + br), qi = 0.5f * (ai + bi);
            float dr = ar - br,          di = ai - bi;
            float kr = 0.5f * di,        ki = -0.5f * dr;  // (A-B)/(2i)
            float pr = (qr * kr + qi * ki) * inv_n;
            float pi = (qi * kr - qr * ki) * inv_n;
            re[p1] = pr;  im[p1] = pi;
            re[p2] = pr;  im[p2] = -pi;                    // Hermitian partner
        }
    }
    if (lane == 0) {                          // f = 0 (DC), both real
        float v = re[0] * im[0] * inv_n;
        re[0] = v; im[0] = 0.f;
    }
    __syncwarp();

    #pragma unroll
    for (int r = 0; r < 16; ++r) {
        int v = swz(lane * 16 + r);
        cre[r] = re[v];  cim[r] = im[v];
    }
    __syncwarp();

    // ---- inverse DIT, layout B ----
    #pragma unroll
    for (int g = 0; g < 8; ++g)            // s=0
        bf_dit1(cre[g * 2], cim[g * 2], cre[g * 2 + 1], cim[g * 2 + 1]);
    #pragma unroll
    for (int g = 0; g < 4; ++g) {          // s=1
        int r = g * 4;
        bf_dit1 (cre[r],     cim[r],     cre[r + 2], cim[r + 2]);
        bf_ditmi(cre[r + 1], cim[r + 1], cre[r + 3], cim[r + 3]);
    }
    #pragma unroll
    for (int g = 0; g < 2; ++g)            // s=2
        #pragma unroll
        for (int j = 0; j < 4; ++j) {
            int r = g * 8 + j;
            if (j == 0)      bf_dit1 (cre[r], cim[r], cre[r + 4], cim[r + 4]);
            else if (j == 2) bf_ditmi(cre[r], cim[r], cre[r + 4], cim[r + 4]);
            else bf_dit(cre[r], cim[r], cre[r + 4], cim[r + 4], C16R[2 * j], C16I[2 * j]);
        }
    #pragma unroll
    for (int r = 0; r < 8; ++r) {          // s=3
        if (r == 0)      bf_dit1 (cre[0], cim[0], cre[8],  cim[8]);
        else if (r == 4) bf_ditmi(cre[4], cim[4], cre[12], cim[12]);
        else bf_dit(cre[r], cim[r], cre[r + 8], cim[r + 8], C16R[r], C16I[r]);
    }
    // ---- transpose B -> A through swizzled SMEM ----
    #pragma unroll
    for (int r = 0; r < 16; ++r) {
        int v = swz(lane * 16 + r);
        re[v] = cre[r];  im[v] = cim[r];
    }
    __syncwarp();
    #pragma unroll
    for (int r = 0; r < 16; ++r) {
        int v = swz(r * 32 + lane);
        cre[r] = re[v];  cim[r] = im[v];
    }
    __syncwarp();
    // ---- inverse: shuffle stage m=16 (conj tw) ----
    {
        float swi, swr;
        __sincosf((float)(lane & 15) * -0.19634954085f, &swi, &swr);
        const float wr = swr, wi = -swi;
        const bool hi = (lane & 16) != 0;
        #pragma unroll
        for (int r = 0; r < 16; ++r) {
            float rr = cre[r] * wr - cim[r] * wi;   // hi lanes pre-rotate b*conj(w)
            float ri = cre[r] * wi + cim[r] * wr;
            float vr = hi ? rr : cre[r];
            float vi = hi ? ri : cim[r];
            float orr = __shfl_xor_sync(0xffffffffu, vr, 16);
            float oii = __shfl_xor_sync(0xffffffffu, vi, 16);
            cre[r] = hi ? (orr - vr) : (vr + orr);
            cim[r] = hi ? (oii - vi) : (vi + oii);
        }
    }
    // ---- inverse DIT, layout A with imag-output pruning ----
    {
        float t2r = t1r * t1r - t1i * t1i, t2i = 2.0f * t1r * t1i;
        float t4r = t2r * t2r - t2i * t2i, t4i = 2.0f * t2r * t2i;
        float t8r = t4r * t4r - t4i * t4i, t8i = 2.0f * t4r * t4i;
        // s=5: g=0 real-only, g>=1 full
        bf_dit_re(cre[0], cre[1], cim[1], t8r, t8i);
        #pragma unroll
        for (int g = 1; g < 8; ++g) {
            int r = g * 2;
            bf_dit(cre[r], cim[r], cre[r + 1], cim[r + 1], t8r, t8i);
        }
        // s=6: g=0 real-only, g>=1 full
        bf_dit_re(cre[0], cre[2], cim[2], t4r, t4i);
        bf_dit_re(cre[1], cre[3], cim[3], t4i, -t4r);
        #pragma unroll
        for (int g = 1; g < 4; ++g) {
            int r = g * 4;
            bf_dit(cre[r],     cim[r],     cre[r + 2], cim[r + 2], t4r, t4i);
            bf_dit(cre[r + 1], cim[r + 1], cre[r + 3], cim[r + 3], t4i, -t4r);
        }
        // s=7: g=0 real-only, g=1 full
        #pragma unroll
        for (int j = 0; j < 4; ++j) {
            float wr = t2r * C16R[2 * j] - t2i * C16I[2 * j];
            float wi = t2r * C16I[2 * j] + t2i * C16R[2 * j];
            bf_dit_re(cre[j], cre[j + 4], cim[j + 4], wr, wi);
        }
        #pragma unroll
        for (int j = 0; j < 4; ++j) {
            float wr = t2r * C16R[2 * j] - t2i * C16I[2 * j];
            float wi = t2r * C16I[2 * j] + t2i * C16R[2 * j];
            int r = 8 + j;
            bf_dit(cre[r], cim[r], cre[r + 4], cim[r + 4], wr, wi);
        }
        // s=8: all real-only
        #pragma unroll
        for (int r = 0; r < 8; ++r) {
            float wr = t1r * C16R[r] - t1i * C16I[r];
            float wi = t1r * C16I[r] + t1i * C16R[r];
            bf_dit_re(cre[r], cre[r + 8], cim[r + 8], wr, wi);
        }
    }
    // corr (natural order) now in cre[], index u = r*32 + lane

    // ---- spill corr row (natural order) for exact value refetch ----
    #pragma unroll
    for (int r = 0; r < 16; ++r)
        re[r * 32 + lane] = cre[r];
    __syncwarp();

    // ---- top-12: position-packed unique keys + strict-less filter + REDUX ----
    unsigned kp[16];
    {
        const int il = 31 - lane;
        #pragma unroll
        for (int r = 0; r < 16; ++r) {
            unsigned u = __float_as_uint(cre[r]);
            unsigned mono = u ^ ((unsigned)((int)u >> 31) | 0x80000000u);
            kp[r] = (mono & 0xFFFFFE00u) | (unsigned)(480 - 32 * r + il);
        }
    }
    int wx[TOPK];
    unsigned Mprev = 0xFFFFFFFFu;
    #pragma unroll
    for (int it = 0; it < TOPK; ++it) {
        unsigned f0  = kp[0]  < Mprev ? kp[0]  : 0u;
        unsigned f1  = kp[1]  < Mprev ? kp[1]  : 0u;
        unsigned f2  = kp[2]  < Mprev ? kp[2]  : 0u;
        unsigned f3  = kp[3]  < Mprev ? kp[3]  : 0u;
        unsigned f4  = kp[4]  < Mprev ? kp[4]  : 0u;
        unsigned f5  = kp[5]  < Mprev ? kp[5]  : 0u;
        unsigned f6  = kp[6]  < Mprev ? kp[6]  : 0u;
        unsigned f7  = kp[7]  < Mprev ? kp[7]  : 0u;
        unsigned f8  = kp[8]  < Mprev ? kp[8]  : 0u;
        unsigned f9  = kp[9]  < Mprev ? kp[9]  : 0u;
        unsigned f10 = kp[10] < Mprev ? kp[10] : 0u;
        unsigned f11 = kp[11] < Mprev ? kp[11] : 0u;
        unsigned f12 = kp[12] < Mprev ? kp[12] : 0u;
        unsigned f13 = kp[13] < Mprev ? kp[13] : 0u;
        unsigned f14 = kp[14] < Mprev ? kp[14] : 0u;
        unsigned f15 = kp[15] < Mprev ? kp[15] : 0u;
        unsigned a0 = max(f0, f1),   a1 = max(f2, f3);
        unsigned a2 = max(f4, f5),   a3 = max(f6, f7);
        unsigned a4 = max(f8, f9),   a5 = max(f10, f11);
        unsigned a6 = max(f12, f13), a7 = max(f14, f15);
        unsigned b0 = max(a0, a1), b1 = max(a2, a3);
        unsigned b2 = max(a4, a5), b3 = max(a6, a7);
        unsigned lmax = max(max(b0, b1), max(b2, b3));
        unsigned M = __reduce_max_sync(0xffffffffu, lmax);
        Mprev = M;
        wx[it] = 511 - (int)(M & 511u);
    }

    // ---- deferred exact-value refetch (kp now dead) + softmax ----
    float wv[TOPK];
    #pragma unroll
    for (int i = 0; i < TOPK; ++i)
        wv[i] = re[wx[i]];                // broadcast LDS
    {
        float mx = wv[0], ssum = 0.f;
        #pragma unroll
        for (int i = 0; i < TOPK; ++i) { wv[i] = __expf(wv[i] - mx); ssum += wv[i]; }
        float inv = 1.0f / ssum;
        #pragma unroll
        for (int i = 0; i < TOPK; ++i) wv[i] *= inv;
    }

    // ---- build V double buffer in the dead FFT tiles (float4 staging) ----
    // even buf (xre row): ev[t] = v[t], ev[512] = ev[513] = v[511]
    // shift buf (xim row): sh[t] = v[t+1] (t<=510), sh[511] = v[511]
    __syncthreads();                          // all warps done with xre/xim + corr rows
    #pragma unroll
    for (int it = 0; it < 4; ++it) {
        int t = t4 + 128 * it;
        unsigned g = base + (unsigned)t * D_DIM + (unsigned)c4;
        float4 v4 = *(const float4*)(V + g);
        xre[(c4 + 0) * PADA + t] = v4.x;  xre[(c4 + 1) * PADA + t] = v4.y;
        xre[(c4 + 2) * PADA + t] = v4.z;  xre[(c4 + 3) * PADA + t] = v4.w;
        if (t > 0) {
            xim[(c4 + 0) * PADA + (t - 1)] = v4.x;
            xim[(c4 + 1) * PADA + (t - 1)] = v4.y;
            xim[(c4 + 2) * PADA + (t - 1)] = v4.z;
            xim[(c4 + 3) * PADA + (t - 1)] = v4.w;
        }
        if (t == 511) {
            #pragma unroll
            for (int j = 0; j < 4; ++j) {
                float vb = (j == 0) ? v4.x : (j == 1) ? v4.y : (j == 2) ? v4.z : v4.w;
                xre[(c4 + j) * PADA + 512] = vb;
                xre[(c4 + j) * PADA + 513] = vb;
                xim[(c4 + j) * PADA + 511] = vb;
            }
        }
    }
    __syncthreads();

    // ---- pair-gather: out[l] = sum_i w_i * v[min(idx_i + l, 511)] ----
    // l = 2*lane + 64*pp; aligned v2 pair from parity-matched buffer.
    {
        unsigned evb = (unsigned)__cvta_generic_to_shared(xre + warp * PADA);
        unsigned shb = (unsigned)__cvta_generic_to_shared(xim + warp * PADA);
        unsigned amaxE = evb + 512u * 4u;     // clamped pair = (v511, v511)
        unsigned amaxO = shb + 510u * 4u;
        unsigned lane8 = (unsigned)lane << 3;

        float acc[16];
        #pragma unroll
        for (int j = 0; j < 16; ++j) acc[j] = 0.f;

        #pragma unroll
        for (int i = 0; i < TOPK; ++i) {
            int idx = wx[i];
            bool odd = (idx & 1) != 0;
            unsigned rowb = odd ? shb : evb;
            unsigned amax = odd ? amaxO : amaxE;
            unsigned ab = rowb + (((unsigned)idx & ~1u) << 2) + lane8;
            float w = wv[i];
            #pragma unroll
            for (int pp = 0; pp < 8; ++pp) {
                unsigned a = ab + (unsigned)(pp * 256);
                a = a < amax ? a : amax;
                float vx, vy;
                asm volatile("ld.shared.v2.f32 {%0, %1}, [%2];"
                             : "=f"(vx), "=f"(vy) : "r"(a));
                acc[2 * pp]     += w * vx;
                acc[2 * pp + 1] += w * vy;
            }
        }
        __syncwarp();                         // all lanes done reading own rows
        #pragma unroll
        for (int pp = 0; pp < 8; ++pp) {      // overwrite own even row with out
            unsigned a = evb + lane8 + (unsigned)(pp * 256);
            asm volatile("st.shared.v2.f32 [%0], {%1, %2};"
                         :: "r"(a), "f"(acc[2 * pp]), "f"(acc[2 * pp + 1]));
        }
    }
    __syncthreads();

    // ---- cooperative coalesced float4 store ----
    #pragma unroll
    for (int it = 0; it < 4; ++it) {
        int t = t4 + 128 * it;
        float4 o4;
        o4.x = xre[(c4 + 0) * PADA + t];
        o4.y = xre[(c4 + 1) * PADA + t];
        o4.z = xre[(c4 + 2) * PADA + t];
        o4.w = xre[(c4 + 3) * PADA + t];
        *(float4*)(out + base + (unsigned)t * D_DIM + (unsigned)c4) = o4;
    }
}

// ---------------------------------------------------------------------------
extern "C" void kernel_launch(void* const* d_in, const int* in_sizes, int n_in,
                              void* d_out, int out_size) {
    (void)n_in; (void)out_size;
    const float* Q = (const float*)d_in[0];
    const float* K = (const float*)d_in[1];
    const float* V = (const float*)d_in[2];
    float* out = (float*)d_out;

    const int B = in_sizes[0] / (L_LEN * D_DIM);   // 16

    const int SMEM = (2 * CPA * PADA) * (int)sizeof(float);   // 33024 B
    cudaFuncSetAttribute(fused_autocorr_kernel,
                         cudaFuncAttributeMaxDynamicSharedMemorySize, SMEM);

    dim3 grid(B * 8, 512 / CPA);   // (128, 64)
    fused_autocorr_kernel<<<grid, 256, SMEM>>>(Q, K, V, out);
}

// round 16
// speedup vs baseline: 1.2823x; 1.0015x over previous
#include <cuda_runtime.h>
#include <math_constants.h>

#define L_LEN  512
#define D_DIM  4096
#define TOPK   12
#define CPA    8           // channels per block
#define PADA   516         // row pitch (%32==4 -> conflict-free coop transpose; even -> 8B align)

__device__ __forceinline__ int brev9(int x) { return (int)(__brev((unsigned)x) >> 23); }
// XOR swizzle: conflict-free for both {r*32+lane} and {lane*16+r} warp patterns
__device__ __forceinline__ int swz(int u)   { return u ^ (u >> 5); }

// 16th roots of unity: C16[j] = exp(-2*pi*i*j/16)
__device__ constexpr float C16R[8] = { 1.0f,  0.92387953251f,  0.70710678119f,  0.38268343236f,
                                       0.0f, -0.38268343236f, -0.70710678119f, -0.92387953251f };
__device__ constexpr float C16I[8] = { 0.0f, -0.38268343236f, -0.70710678119f, -0.92387953251f,
                                      -1.0f, -0.92387953251f, -0.70710678119f, -0.38268343236f };

// DIF butterfly: (a,b) -> (a+b, (a-b)*w)
__device__ __forceinline__ void bf_dif(float& ar, float& ai, float& br, float& bi,
                                       float wr, float wi) {
    float tr = ar - br, ti = ai - bi;
    ar += br; ai += bi;
    br = tr * wr - ti * wi;
    bi = tr * wi + ti * wr;
}
__device__ __forceinline__ void bf_dif1(float& ar, float& ai, float& br, float& bi) {
    float tr = ar - br, ti = ai - bi;
    ar += br; ai += bi; br = tr; bi = ti;
}
__device__ __forceinline__ void bf_difmi(float& ar, float& ai, float& br, float& bi) {
    float tr = ar - br, ti = ai - bi;        // *( -i ): (tr,ti) -> (ti, -tr)
    ar += br; ai += bi; br = ti; bi = -tr;
}
// DIT (inverse) butterfly with conj(w): (a,b) -> (a + b*conj(w), a - b*conj(w))
__device__ __forceinline__ void bf_dit(float& ar, float& ai, float& br, float& bi,
                                       float wr, float wi) {
    float rr = br * wr + bi * wi;
    float ri = bi * wr - br * wi;
    br = ar - rr; bi = ai - ri;
    ar += rr; ai += ri;
}
__device__ __forceinline__ void bf_dit1(float& ar, float& ai, float& br, float& bi) {
    float rr = br, ri = bi;
    br = ar - rr; bi = ai - ri;
    ar += rr; ai += ri;
}
__device__ __forceinline__ void bf_ditmi(float& ar, float& ai, float& br, float& bi) {
    float rr = -bi, ri = br;                 // b * conj(-i) = b * i
    br = ar - rr; bi = ai - ri;
    ar += rr; ai += ri;
}
// real-output-only DIT butterfly: imag outputs dropped (inputs still complex)
__device__ __forceinline__ void bf_dit_re(float& ar, float& br, float bi,
                                          float wr, float wi) {
    float rr = br * wr + bi * wi;
    br = ar - rr;
    ar += rr;
}

// ---------------------------------------------------------------------------
// Fused: per-channel FFT cross-correlation -> top-12 + softmax -> gather of V.
// One warp per channel, 8 channels / 256 threads, 2 smem tiles total.
// Cross-spectrum via SMEM paired RMW (only non-spilling shape; R7/R11).
// Inverse FFT tail prunes imaginary outputs (only real corr is consumed).
// Converged structure: 276.6us / 276.9us across two confirmation runs,
// 4.9x over the first correct kernel (1354us).
// ---------------------------------------------------------------------------
extern "C" __global__ void __launch_bounds__(256, 5)
fused_autocorr_kernel(const float* __restrict__ Q, const float* __restrict__ K,
                      const float* __restrict__ V, float* __restrict__ out) {
    extern __shared__ float smbuf[];
    float* xre = smbuf;                    // [CPA][PADA]  FFT re / V even buf / out tile
    float* xim = xre + CPA * PADA;         // [CPA][PADA]  FFT im / V shift buf

    const int tid  = threadIdx.x;
    const int warp = tid >> 5;
    const int lane = tid & 31;
    const int bh   = blockIdx.x;
    const int b    = bh >> 3;
    const int h    = bh & 7;
    const int cbase = blockIdx.y * CPA;

    // 32-bit global offsets (all tensors < 2^27 elements)
    const unsigned base = (unsigned)b * (L_LEN * D_DIM) + (unsigned)h * 512 + (unsigned)cbase;
    const int c4 = (tid & 1) << 2;          // 0 or 4
    const int t4 = tid >> 1;                // 0..127

    // cooperative float4 coalesced loads (Q,K), transposed channel-major
    #pragma unroll
    for (int it = 0; it < 4; ++it) {
        int t = t4 + 128 * it;
        unsigned g = base + (unsigned)t * D_DIM + (unsigned)c4;
        float4 q4 = *(const float4*)(Q + g);
        float4 k4 = *(const float4*)(K + g);
        xre[(c4 + 0) * PADA + t] = q4.x;  xre[(c4 + 1) * PADA + t] = q4.y;
        xre[(c4 + 2) * PADA + t] = q4.z;  xre[(c4 + 3) * PADA + t] = q4.w;
        xim[(c4 + 0) * PADA + t] = k4.x;  xim[(c4 + 1) * PADA + t] = k4.y;
        xim[(c4 + 2) * PADA + t] = k4.z;  xim[(c4 + 3) * PADA + t] = k4.w;
    }
    __syncthreads();

    float* re = xre + warp * PADA;
    float* im = xim + warp * PADA;

    // base twiddle: t1 = w^lane, w = exp(-2*pi*i/512)
    float t1i, t1r;
    __sincosf((float)lane * -0.01227184630f, &t1i, &t1r);

    // load channel into registers, layout A (u = r*32 + lane)
    float cre[16], cim[16];
    #pragma unroll
    for (int r = 0; r < 16; ++r) {
        cre[r] = re[r * 32 + lane];
        cim[r] = im[r * 32 + lane];
    }
    __syncwarp();

    // ---- forward DIF, layout A ----
    #pragma unroll
    for (int r = 0; r < 8; ++r) {          // s=8, m=256
        float wr = t1r * C16R[r] - t1i * C16I[r];
        float wi = t1r * C16I[r] + t1i * C16R[r];
        bf_dif(cre[r], cim[r], cre[r + 8], cim[r + 8], wr, wi);
    }
    {                                       // s=7..5 (bases recomputed from t1)
        float t2r = t1r * t1r - t1i * t1i, t2i = 2.0f * t1r * t1i;
        #pragma unroll
        for (int g = 0; g < 2; ++g)
            #pragma unroll
            for (int j = 0; j < 4; ++j) {
                float wr = t2r * C16R[2 * j] - t2i * C16I[2 * j];
                float wi = t2r * C16I[2 * j] + t2i * C16R[2 * j];
                int r = g * 8 + j;
                bf_dif(cre[r], cim[r], cre[r + 4], cim[r + 4], wr, wi);
            }
        float t4r = t2r * t2r - t2i * t2i, t4i = 2.0f * t2r * t2i;   // s=6
        #pragma unroll
        for (int g = 0; g < 4; ++g) {
            int r = g * 4;
            bf_dif(cre[r],     cim[r],     cre[r + 2], cim[r + 2], t4r, t4i);
            bf_dif(cre[r + 1], cim[r + 1], cre[r + 3], cim[r + 3], t4i, -t4r);
        }
        float t8r = t4r * t4r - t4i * t4i, t8i = 2.0f * t4r * t4i;   // s=5
        #pragma unroll
        for (int g = 0; g < 8; ++g) {
            int r = g * 2;
            bf_dif(cre[r], cim[r], cre[r + 1], cim[r + 1], t8r, t8i);
        }
    }
    // ---- forward: shuffle stage m=16 ----
    {
        float swi, swr;
        __sincosf((float)(lane & 15) * -0.19634954085f, &swi, &swr);
        const bool hi = (lane & 16) != 0;
        #pragma unroll
        for (int r = 0; r < 16; ++r) {
            float orr = __shfl_xor_sync(0xffffffffu, cre[r], 16);
            float oii = __shfl_xor_sync(0xffffffffu, cim[r], 16);
            float sr = cre[r] + orr, si = cim[r] + oii;
            float tr = orr - cre[r], ti = oii - cim[r];    // (a-b) on hi lanes
            float pr = tr * swr - ti * swi;
            float pi = tr * swi + ti * swr;
            cre[r] = hi ? pr : sr;
            cim[r] = hi ? pi : si;
        }
    }
    // ---- transpose A -> B through swizzled SMEM ----
    #pragma unroll
    for (int r = 0; r < 16; ++r) {
        int v = swz(r * 32 + lane);
        re[v] = cre[r];  im[v] = cim[r];
    }
    __syncwarp();
    #pragma unroll
    for (int r = 0; r < 16; ++r) {
        int v = swz(lane * 16 + r);
        cre[r] = re[v];  cim[r] = im[v];
    }
    __syncwarp();
    // ---- forward DIF, layout B (all-constant twiddles) ----
    #pragma unroll
    for (int r = 0; r < 8; ++r) {          // s=3, m=8
        if (r == 0)      bf_dif1 (cre[0], cim[0], cre[8],  cim[8]);
        else if (r == 4) bf_difmi(cre[4], cim[4], cre[12], cim[12]);
        else bf_dif(cre[r], cim[r], cre[r + 8], cim[r + 8], C16R[r], C16I[r]);
    }
    #pragma unroll
    for (int g = 0; g < 2; ++g)            // s=2, m=4
        #pragma unroll
        for (int j = 0; j < 4; ++j) {
            int r = g * 8 + j;
            if (j == 0)      bf_dif1 (cre[r], cim[r], cre[r + 4], cim[r + 4]);
            else if (j == 2) bf_difmi(cre[r], cim[r], cre[r + 4], cim[r + 4]);
            else bf_dif(cre[r], cim[r], cre[r + 4], cim[r + 4], C16R[2 * j], C16I[2 * j]);
        }
    #pragma unroll
    for (int g = 0; g < 4; ++g) {          // s=1, m=2
        int r = g * 4;
        bf_dif1 (cre[r],     cim[r],     cre[r + 2], cim[r + 2]);
        bf_difmi(cre[r + 1], cim[r + 1], cre[r + 3], cim[r + 3]);
    }
    #pragma unroll
    for (int g = 0; g < 8; ++g)            // s=0, m=1
        bf_dif1(cre[g * 2], cim[g * 2], cre[g * 2 + 1], cim[g * 2 + 1]);

    // ---- spill (layout B) for bit-reversed Hermitian cross-spectrum ----
    #pragma unroll
    for (int r = 0; r < 16; ++r) {
        int v = swz(lane * 16 + r);
        re[v] = cre[r];  im[v] = cim[r];
    }
    __syncwarp();

    const float inv_n = 1.0f / 512.0f;
    #pragma unroll
    for (int k = 0; k < 8; ++k) {
        int f = 1 + lane + (k << 5);          // f in [1, 256]
        if (f == 256) {
            int pb = swz(brev9(256));
            float qr = re[pb], kr = im[pb];   // both real at Nyquist
            re[pb] = qr * kr * inv_n;
            im[pb] = 0.f;
        } else {
            int p1 = swz(brev9(f));
            int p2 = swz(brev9(512 - f));
            float ar = re[p1], ai = im[p1];
            float br = re[p2], bi = -im[p2];              // conj(X[512-f])
            float qr = 0.5f * (ar + br), qi = 0.5f * (ai + bi);
            float dr = ar - br,          di = ai - bi;
            float kr = 0.5f * di,        ki = -0.5f * dr;  // (A-B)/(2i)
            float pr = (qr * kr + qi * ki) * inv_n;
            float pi = (qi * kr - qr * ki) * inv_n;
            re[p1] = pr;  im[p1] = pi;
            re[p2] = pr;  im[p2] = -pi;                    // Hermitian partner
        }
    }
    if (lane == 0) {                          // f = 0 (DC), both real
        float v = re[0] * im[0] * inv_n;
        re[0] = v; im[0] = 0.f;
    }
    __syncwarp();

    #pragma unroll
    for (int r = 0; r < 16; ++r) {
        int v = swz(lane * 16 + r);
        cre[r] = re[v];  cim[r] = im[v];
    }
    __syncwarp();

    // ---- inverse DIT, layout B ----
    #pragma unroll
    for (int g = 0; g < 8; ++g)            // s=0
        bf_dit1(cre[g * 2], cim[g * 2], cre[g * 2 + 1], cim[g * 2 + 1]);
    #pragma unroll
    for (int g = 0; g < 4; ++g) {          // s=1
        int r = g * 4;
        bf_dit1 (cre[r],     cim[r],     cre[r + 2], cim[r + 2]);
        bf_ditmi(cre[r + 1], cim[r + 1], cre[r + 3], cim[r + 3]);
    }
    #pragma unroll
    for (int g = 0; g < 2; ++g)            // s=2
        #pragma unroll
        for (int j = 0; j < 4; ++j) {
            int r = g * 8 + j;
            if (j == 0)      bf_dit1 (cre[r], cim[r], cre[r + 4], cim[r + 4]);
            else if (j == 2) bf_ditmi(cre[r], cim[r], cre[r + 4], cim[r + 4]);
            else bf_dit(cre[r], cim[r], cre[r + 4], cim[r + 4], C16R[2 * j], C16I[2 * j]);
        }
    #pragma unroll
    for (int r = 0; r < 8; ++r) {          // s=3
        if (r == 0)      bf_dit1 (cre[0], cim[0], cre[8],  cim[8]);
        else if (r == 4) bf_ditmi(cre[4], cim[4], cre[12], cim[12]);
        else bf_dit(cre[r], cim[r], cre[r + 8], cim[r + 8], C16R[r], C16I[r]);
    }
    // ---- transpose B -> A through swizzled SMEM ----
    #pragma unroll
    for (int r = 0; r < 16; ++r) {
        int v = swz(lane * 16 + r);
        re[v] = cre[r];  im[v] = cim[r];
    }
    __syncwarp();
    #pragma unroll
    for (int r = 0; r < 16; ++r) {
        int v = swz(r * 32 + lane);
        cre[r] = re[v];  cim[r] = im[v];
    }
    __syncwarp();
    // ---- inverse: shuffle stage m=16 (conj tw) ----
    {
        float swi, swr;
        __sincosf((float)(lane & 15) * -0.19634954085f, &swi, &swr);
        const float wr = swr, wi = -swi;
        const bool hi = (lane & 16) != 0;
        #pragma unroll
        for (int r = 0; r < 16; ++r) {
            float rr = cre[r] * wr - cim[r] * wi;   // hi lanes pre-rotate b*conj(w)
            float ri = cre[r] * wi + cim[r] * wr;
            float vr = hi ? rr : cre[r];
            float vi = hi ? ri : cim[r];
            float orr = __shfl_xor_sync(0xffffffffu, vr, 16);
            float oii = __shfl_xor_sync(0xffffffffu, vi, 16);
            cre[r] = hi ? (orr - vr) : (vr + orr);
            cim[r] = hi ? (oii - vi) : (vi + oii);
        }
    }
    // ---- inverse DIT, layout A with imag-output pruning ----
    {
        float t2r = t1r * t1r - t1i * t1i, t2i = 2.0f * t1r * t1i;
        float t4r = t2r * t2r - t2i * t2i, t4i = 2.0f * t2r * t2i;
        float t8r = t4r * t4r - t4i * t4i, t8i = 2.0f * t4r * t4i;
        // s=5: g=0 real-only, g>=1 full
        bf_dit_re(cre[0], cre[1], cim[1], t8r, t8i);
        #pragma unroll
        for (int g = 1; g < 8; ++g) {
            int r = g * 2;
            bf_dit(cre[r], cim[r], cre[r + 1], cim[r + 1], t8r, t8i);
        }
        // s=6: g=0 real-only, g>=1 full
        bf_dit_re(cre[0], cre[2], cim[2], t4r, t4i);
        bf_dit_re(cre[1], cre[3], cim[3], t4i, -t4r);
        #pragma unroll
        for (int g = 1; g < 4; ++g) {
            int r = g * 4;
            bf_dit(cre[r],     cim[r],     cre[r + 2], cim[r + 2], t4r, t4i);
            bf_dit(cre[r + 1], cim[r + 1], cre[r + 3], cim[r + 3], t4i, -t4r);
        }
        // s=7: g=0 real-only, g=1 full
        #pragma unroll
        for (int j = 0; j < 4; ++j) {
            float wr = t2r * C16R[2 * j] - t2i * C16I[2 * j];
            float wi = t2r * C16I[2 * j] + t2i * C16R[2 * j];
            bf_dit_re(cre[j], cre[j + 4], cim[j + 4], wr, wi);
        }
        #pragma unroll
        for (int j = 0; j < 4; ++j) {
            float wr = t2r * C16R[2 * j] - t2i * C16I[2 * j];
            float wi = t2r * C16I[2 * j] + t2i * C16R[2 * j];
            int r = 8 + j;
            bf_dit(cre[r], cim[r], cre[r + 4], cim[r + 4], wr, wi);
        }
        // s=8: all real-only
        #pragma unroll
        for (int r = 0; r < 8; ++r) {
            float wr = t1r * C16R[r] - t1i * C16I[r];
            float wi = t1r * C16I[r] + t1i * C16R[r];
            bf_dit_re(cre[r], cre[r + 8], cim[r + 8], wr, wi);
        }
    }
    // corr (natural order) now in cre[], index u = r*32 + lane

    // ---- spill corr row (natural order) for exact value refetch ----
    #pragma unroll
    for (int r = 0; r < 16; ++r)
        re[r * 32 + lane] = cre[r];
    __syncwarp();

    // ---- top-12: position-packed unique keys + strict-less filter + REDUX ----
    unsigned kp[16];
    {
        const int il = 31 - lane;
        #pragma unroll
        for (int r = 0; r < 16; ++r) {
            unsigned u = __float_as_uint(cre[r]);
            unsigned mono = u ^ ((unsigned)((int)u >> 31) | 0x80000000u);
            kp[r] = (mono & 0xFFFFFE00u) | (unsigned)(480 - 32 * r + il);
        }
    }
    int wx[TOPK];
    unsigned Mprev = 0xFFFFFFFFu;
    #pragma unroll
    for (int it = 0; it < TOPK; ++it) {
        unsigned f0  = kp[0]  < Mprev ? kp[0]  : 0u;
        unsigned f1  = kp[1]  < Mprev ? kp[1]  : 0u;
        unsigned f2  = kp[2]  < Mprev ? kp[2]  : 0u;
        unsigned f3  = kp[3]  < Mprev ? kp[3]  : 0u;
        unsigned f4  = kp[4]  < Mprev ? kp[4]  : 0u;
        unsigned f5  = kp[5]  < Mprev ? kp[5]  : 0u;
        unsigned f6  = kp[6]  < Mprev ? kp[6]  : 0u;
        unsigned f7  = kp[7]  < Mprev ? kp[7]  : 0u;
        unsigned f8  = kp[8]  < Mprev ? kp[8]  : 0u;
        unsigned f9  = kp[9]  < Mprev ? kp[9]  : 0u;
        unsigned f10 = kp[10] < Mprev ? kp[10] : 0u;
        unsigned f11 = kp[11] < Mprev ? kp[11] : 0u;
        unsigned f12 = kp[12] < Mprev ? kp[12] : 0u;
        unsigned f13 = kp[13] < Mprev ? kp[13] : 0u;
        unsigned f14 = kp[14] < Mprev ? kp[14] : 0u;
        unsigned f15 = kp[15] < Mprev ? kp[15] : 0u;
        unsigned a0 = max(f0, f1),   a1 = max(f2, f3);
        unsigned a2 = max(f4, f5),   a3 = max(f6, f7);
        unsigned a4 = max(f8, f9),   a5 = max(f10, f11);
        unsigned a6 = max(f12, f13), a7 = max(f14, f15);
        unsigned b0 = max(a0, a1), b1 = max(a2, a3);
        unsigned b2 = max(a4, a5), b3 = max(a6, a7);
        unsigned lmax = max(max(b0, b1), max(b2, b3));
        unsigned M = __reduce_max_sync(0xffffffffu, lmax);
        Mprev = M;
        wx[it] = 511 - (int)(M & 511u);
    }

    // ---- deferred exact-value refetch (kp now dead) + softmax ----
    float wv[TOPK];
    #pragma unroll
    for (int i = 0; i < TOPK; ++i)
        wv[i] = re[wx[i]];                // broadcast LDS
    {
        float mx = wv[0], ssum = 0.f;
        #pragma unroll
        for (int i = 0; i < TOPK; ++i) { wv[i] = __expf(wv[i] - mx); ssum += wv[i]; }
        float inv = 1.0f / ssum;
        #pragma unroll
        for (int i = 0; i < TOPK; ++i) wv[i] *= inv;
    }

    // ---- build V double buffer in the dead FFT tiles (float4 staging) ----
    // even buf (xre row): ev[t] = v[t], ev[512] = ev[513] = v[511]
    // shift buf (xim row): sh[t] = v[t+1] (t<=510), sh[511] = v[511]
    __syncthreads();                          // all warps done with xre/xim + corr rows
    #pragma unroll
    for (int it = 0; it < 4; ++it) {
        int t = t4 + 128 * it;
        unsigned g = base + (unsigned)t * D_DIM + (unsigned)c4;
        float4 v4 = *(const float4*)(V + g);
        xre[(c4 + 0) * PADA + t] = v4.x;  xre[(c4 + 1) * PADA + t] = v4.y;
        xre[(c4 + 2) * PADA + t] = v4.z;  xre[(c4 + 3) * PADA + t] = v4.w;
        if (t > 0) {
            xim[(c4 + 0) * PADA + (t - 1)] = v4.x;
            xim[(c4 + 1) * PADA + (t - 1)] = v4.y;
            xim[(c4 + 2) * PADA + (t - 1)] = v4.z;
            xim[(c4 + 3) * PADA + (t - 1)] = v4.w;
        }
        if (t == 511) {
            #pragma unroll
            for (int j = 0; j < 4; ++j) {
                float vb = (j == 0) ? v4.x : (j == 1) ? v4.y : (j == 2) ? v4.z : v4.w;
                xre[(c4 + j) * PADA + 512] = vb;
                xre[(c4 + j) * PADA + 513] = vb;
                xim[(c4 + j) * PADA + 511] = vb;
            }
        }
    }
    __syncthreads();

    // ---- pair-gather: out[l] = sum_i w_i * v[min(idx_i + l, 511)] ----
    // l = 2*lane + 64*pp; aligned v2 pair from parity-matched buffer.
    {
        unsigned evb = (unsigned)__cvta_generic_to_shared(xre + warp * PADA);
        unsigned shb = (unsigned)__cvta_generic_to_shared(xim + warp * PADA);
        unsigned amaxE = evb + 512u * 4u;     // clamped pair = (v511, v511)
        unsigned amaxO = shb + 510u * 4u;
        unsigned lane8 = (unsigned)lane << 3;

        float acc[16];
        #pragma unroll
        for (int j = 0; j < 16; ++j) acc[j] = 0.f;

        #pragma unroll
        for (int i = 0; i < TOPK; ++i) {
            int idx = wx[i];
            bool odd = (idx & 1) != 0;
            unsigned rowb = odd ? shb : evb;
            unsigned amax = odd ? amaxO : amaxE;
            unsigned ab = rowb + (((unsigned)idx & ~1u) << 2) + lane8;
            float w = wv[i];
            #pragma unroll
            for (int pp = 0; pp < 8; ++pp) {
                unsigned a = ab + (unsigned)(pp * 256);
                a = a < amax ? a : amax;
                float vx, vy;
                asm volatile("ld.shared.v2.f32 {%0, %1}, [%2];"
                             : "=f"(vx), "=f"(vy) : "r"(a));
                acc[2 * pp]     += w * vx;
                acc[2 * pp + 1] += w * vy;
            }
        }
        __syncwarp();                         // all lanes done reading own rows
        #pragma unroll
        for (int pp = 0; pp < 8; ++pp) {      // overwrite own even row with out
            unsigned a = evb + lane8 + (unsigned)(pp * 256);
            asm volatile("st.shared.v2.f32 [%0], {%1, %2};"
                         :: "r"(a), "f"(acc[2 * pp]), "f"(acc[2 * pp + 1]));
        }
    }
    __syncthreads();

    // ---- cooperative coalesced float4 store ----
    #pragma unroll
    for (int it = 0; it < 4; ++it) {
        int t = t4 + 128 * it;
        float4 o4;
        o4.x = xre[(c4 + 0) * PADA + t];
        o4.y = xre[(c4 + 1) * PADA + t];
        o4.z = xre[(c4 + 2) * PADA + t];
        o4.w = xre[(c4 + 3) * PADA + t];
        *(float4*)(out + base + (unsigned)t * D_DIM + (unsigned)c4) = o4;
    }
}

// ---------------------------------------------------------------------------
extern "C" void kernel_launch(void* const* d_in, const int* in_sizes, int n_in,
                              void* d_out, int out_size) {
    (void)n_in; (void)out_size;
    const float* Q = (const float*)d_in[0];
    const float* K = (const float*)d_in[1];
    const float* V = (const float*)d_in[2];
    float* out = (float*)d_out;

    const int B = in_sizes[0] / (L_LEN * D_DIM);   // 16

    const int SMEM = (2 * CPA * PADA) * (int)sizeof(float);   // 33024 B
    cudaFuncSetAttribute(fused_autocorr_kernel,
                         cudaFuncAttributeMaxDynamicSharedMemorySize, SMEM);

    dim3 grid(B * 8, 512 / CPA);   // (128, 64)
    fused_autocorr_kernel<<<grid, 256, SMEM>>>(Q, K, V, out);
}